// round 1
// baseline (speedup 1.0000x reference)
#include <cuda_runtime.h>
#include <math.h>

#define N_NODES 50000
#define N_EDGES 800000
#define N_GRAPHS 512
#define D_IN 128
#define D_EDGE 32
#define D_HID 128
#define D_GLOB 64
#define K1 (2*D_IN + D_EDGE)   /* 288 */

// Scratch (device globals: no allocation allowed)
__device__ float g_agg[N_NODES * D_HID];     // 25.6 MB
__device__ float g_pooled[N_GRAPHS * D_HID];
__device__ float g_counts[N_GRAPHS];

// ---------------------------------------------------------------------------
__global__ void zero_kernel() {
    int idx = blockIdx.x * blockDim.x + threadIdx.x;
    int stride = gridDim.x * blockDim.x;
    for (int i = idx; i < N_NODES * D_HID; i += stride) g_agg[i] = 0.0f;
    for (int i = idx; i < N_GRAPHS * D_HID; i += stride) g_pooled[i] = 0.0f;
    for (int i = idx; i < N_GRAPHS; i += stride) g_counts[i] = 0.0f;
}

// ---------------------------------------------------------------------------
// Edge block: msg = relu(relu([src|dst|ea] @ We1 + be1) @ We2 + be2)
// then atomic scatter-add into g_agg[dst].
// Tile: 32 edges x 128 cols per block, 256 threads.
// warp w owns edges [4w, 4w+4); lane owns cols [4*lane, 4*lane+4).
// ---------------------------------------------------------------------------
#define TE 32
#define BK 32

__global__ __launch_bounds__(256) void edge_kernel(
    const float* __restrict__ x, const int* __restrict__ eidx,
    const float* __restrict__ ea,
    const float* __restrict__ We1, const float* __restrict__ be1,
    const float* __restrict__ We2, const float* __restrict__ be2)
{
    __shared__ int   sSrc[TE], sDst[TE];
    __shared__ float sA[TE * (BK + 1)];        // 32 x 33
    __shared__ float sB[BK * D_HID];           // 32 x 128
    __shared__ float sH[TE * (D_HID + 4)];     // 32 x 132
    __shared__ float sB1[D_HID], sB2[D_HID];

    const int tid  = threadIdx.x;
    const int warp = tid >> 5;
    const int lane = tid & 31;
    const int eBase = blockIdx.x * TE;

    if (tid < TE) {
        sSrc[tid] = eidx[eBase + tid];
        sDst[tid] = eidx[N_EDGES + eBase + tid];
    }
    if (tid < D_HID) { sB1[tid] = be1[tid]; sB2[tid] = be2[tid]; }
    __syncthreads();

    // ---- layer 1: K = 288 ----
    float acc[4][4] = {};
    for (int k0 = 0; k0 < K1; k0 += BK) {
        // stage A chunk [32 edges x 32 k] (gathered)
        #pragma unroll
        for (int r = 0; r < 4; r++) {
            int idx = tid + r * 256;            // 0..1023
            int e = idx >> 5, k = idx & 31;
            int gk = k0 + k;
            float v;
            if (gk < D_IN)            v = x[sSrc[e] * D_IN + gk];
            else if (gk < 2 * D_IN)   v = x[sDst[e] * D_IN + (gk - D_IN)];
            else                      v = ea[(eBase + e) * D_EDGE + (gk - 2 * D_IN)];
            sA[e * (BK + 1) + k] = v;
        }
        // stage B chunk [32 k x 128]
        {
            const float4* s4 = (const float4*)(We1 + (size_t)k0 * D_HID);
            float4* d4 = (float4*)sB;
            #pragma unroll
            for (int r = 0; r < 4; r++) d4[tid + r * 256] = s4[tid + r * 256];
        }
        __syncthreads();
        #pragma unroll
        for (int kk = 0; kk < BK; kk++) {
            float a0 = sA[(warp * 4 + 0) * (BK + 1) + kk];
            float a1 = sA[(warp * 4 + 1) * (BK + 1) + kk];
            float a2 = sA[(warp * 4 + 2) * (BK + 1) + kk];
            float a3 = sA[(warp * 4 + 3) * (BK + 1) + kk];
            float4 b = ((const float4*)(sB + kk * D_HID))[lane];
            acc[0][0] += a0 * b.x; acc[0][1] += a0 * b.y; acc[0][2] += a0 * b.z; acc[0][3] += a0 * b.w;
            acc[1][0] += a1 * b.x; acc[1][1] += a1 * b.y; acc[1][2] += a1 * b.z; acc[1][3] += a1 * b.w;
            acc[2][0] += a2 * b.x; acc[2][1] += a2 * b.y; acc[2][2] += a2 * b.z; acc[2][3] += a2 * b.w;
            acc[3][0] += a3 * b.x; acc[3][1] += a3 * b.y; acc[3][2] += a3 * b.z; acc[3][3] += a3 * b.w;
        }
        __syncthreads();
    }
    // bias + relu -> sH
    #pragma unroll
    for (int i = 0; i < 4; i++) {
        int e = warp * 4 + i;
        float4 h;
        h.x = fmaxf(acc[i][0] + sB1[lane * 4 + 0], 0.0f);
        h.y = fmaxf(acc[i][1] + sB1[lane * 4 + 1], 0.0f);
        h.z = fmaxf(acc[i][2] + sB1[lane * 4 + 2], 0.0f);
        h.w = fmaxf(acc[i][3] + sB1[lane * 4 + 3], 0.0f);
        ((float4*)(sH + e * (D_HID + 4)))[lane] = h;
    }
    __syncthreads();

    // ---- layer 2: K = 128 ----
    float acc2[4][4] = {};
    for (int k0 = 0; k0 < D_HID; k0 += BK) {
        const float4* s4 = (const float4*)(We2 + (size_t)k0 * D_HID);
        float4* d4 = (float4*)sB;
        #pragma unroll
        for (int r = 0; r < 4; r++) d4[tid + r * 256] = s4[tid + r * 256];
        __syncthreads();
        #pragma unroll
        for (int kk = 0; kk < BK; kk++) {
            int k = k0 + kk;
            float a0 = sH[(warp * 4 + 0) * (D_HID + 4) + k];
            float a1 = sH[(warp * 4 + 1) * (D_HID + 4) + k];
            float a2 = sH[(warp * 4 + 2) * (D_HID + 4) + k];
            float a3 = sH[(warp * 4 + 3) * (D_HID + 4) + k];
            float4 b = ((const float4*)(sB + kk * D_HID))[lane];
            acc2[0][0] += a0 * b.x; acc2[0][1] += a0 * b.y; acc2[0][2] += a0 * b.z; acc2[0][3] += a0 * b.w;
            acc2[1][0] += a1 * b.x; acc2[1][1] += a1 * b.y; acc2[1][2] += a1 * b.z; acc2[1][3] += a1 * b.w;
            acc2[2][0] += a2 * b.x; acc2[2][1] += a2 * b.y; acc2[2][2] += a2 * b.z; acc2[2][3] += a2 * b.w;
            acc2[3][0] += a3 * b.x; acc2[3][1] += a3 * b.y; acc2[3][2] += a3 * b.z; acc2[3][3] += a3 * b.w;
        }
        __syncthreads();
    }
    // relu + atomic scatter into g_agg[dst]
    #pragma unroll
    for (int i = 0; i < 4; i++) {
        int e = warp * 4 + i;
        int dst = sDst[e];
        #pragma unroll
        for (int j = 0; j < 4; j++) {
            float v = fmaxf(acc2[i][j] + sB2[lane * 4 + j], 0.0f);
            atomicAdd(&g_agg[dst * D_HID + lane * 4 + j], v);
        }
    }
}

// ---------------------------------------------------------------------------
// Node block: cat = [x | agg]; gate = sigmoid(cat@Wg+bg) -> x_weights output;
// x_new = gate * relu(cat@Wn+bn) -> pooled atomic sums + counts.
// ---------------------------------------------------------------------------
__global__ __launch_bounds__(256) void node_kernel(
    const float* __restrict__ x,
    const float* __restrict__ Wg, const float* __restrict__ bg,
    const float* __restrict__ Wn, const float* __restrict__ bn,
    const int* __restrict__ batch, float* __restrict__ xw_out)
{
    __shared__ float sA[TE * (BK + 1)];
    __shared__ float sB[BK * D_HID];
    __shared__ float sG[TE * (D_HID + 4)];
    __shared__ float sBias[D_HID];
    __shared__ int   sBatch[TE];

    const int tid  = threadIdx.x;
    const int warp = tid >> 5;
    const int lane = tid & 31;
    const int nBase = blockIdx.x * TE;

    if (tid < TE) sBatch[tid] = (nBase + tid < N_NODES) ? batch[nBase + tid] : 0;

    for (int pass = 0; pass < 2; pass++) {
        const float* W = pass ? Wn : Wg;
        const float* b = pass ? bn : bg;
        if (tid < D_HID) sBias[tid] = b[tid];

        float acc[4][4] = {};
        for (int k0 = 0; k0 < 2 * D_HID; k0 += BK) {
            #pragma unroll
            for (int r = 0; r < 4; r++) {
                int idx = tid + r * 256;
                int e = idx >> 5, k = idx & 31;
                int gk = k0 + k;
                int n = nBase + e;
                float v = 0.0f;
                if (n < N_NODES)
                    v = (gk < D_IN) ? x[n * D_IN + gk]
                                    : g_agg[n * D_HID + (gk - D_IN)];
                sA[e * (BK + 1) + k] = v;
            }
            {
                const float4* s4 = (const float4*)(W + (size_t)k0 * D_HID);
                float4* d4 = (float4*)sB;
                #pragma unroll
                for (int r = 0; r < 4; r++) d4[tid + r * 256] = s4[tid + r * 256];
            }
            __syncthreads();
            #pragma unroll
            for (int kk = 0; kk < BK; kk++) {
                float a0 = sA[(warp * 4 + 0) * (BK + 1) + kk];
                float a1 = sA[(warp * 4 + 1) * (BK + 1) + kk];
                float a2 = sA[(warp * 4 + 2) * (BK + 1) + kk];
                float a3 = sA[(warp * 4 + 3) * (BK + 1) + kk];
                float4 bb = ((const float4*)(sB + kk * D_HID))[lane];
                acc[0][0] += a0 * bb.x; acc[0][1] += a0 * bb.y; acc[0][2] += a0 * bb.z; acc[0][3] += a0 * bb.w;
                acc[1][0] += a1 * bb.x; acc[1][1] += a1 * bb.y; acc[1][2] += a1 * bb.z; acc[1][3] += a1 * bb.w;
                acc[2][0] += a2 * bb.x; acc[2][1] += a2 * bb.y; acc[2][2] += a2 * bb.z; acc[2][3] += a2 * bb.w;
                acc[3][0] += a3 * bb.x; acc[3][1] += a3 * bb.y; acc[3][2] += a3 * bb.z; acc[3][3] += a3 * bb.w;
            }
            __syncthreads();
        }

        if (pass == 0) {
            #pragma unroll
            for (int i = 0; i < 4; i++) {
                int e = warp * 4 + i;
                int n = nBase + e;
                #pragma unroll
                for (int j = 0; j < 4; j++) {
                    int col = lane * 4 + j;
                    float g = 1.0f / (1.0f + expf(-(acc[i][j] + sBias[col])));
                    sG[e * (D_HID + 4) + col] = g;
                    if (n < N_NODES) xw_out[(size_t)n * D_HID + col] = g;
                }
            }
            if (lane == 0) {
                #pragma unroll
                for (int i = 0; i < 4; i++) {
                    int n = nBase + warp * 4 + i;
                    if (n < N_NODES) atomicAdd(&g_counts[sBatch[warp * 4 + i]], 1.0f);
                }
            }
            __syncthreads();
        } else {
            #pragma unroll
            for (int i = 0; i < 4; i++) {
                int e = warp * 4 + i;
                int n = nBase + e;
                int gidx = sBatch[e];
                #pragma unroll
                for (int j = 0; j < 4; j++) {
                    int col = lane * 4 + j;
                    float v = fmaxf(acc[i][j] + sBias[col], 0.0f);
                    float xn = sG[e * (D_HID + 4) + col] * v;
                    if (n < N_NODES) atomicAdd(&g_pooled[gidx * D_HID + col], xn);
                }
            }
        }
    }
}

// ---------------------------------------------------------------------------
// Global block: u_new = relu([u | pooled_mean] @ Wu + bu)
// ---------------------------------------------------------------------------
__global__ __launch_bounds__(64) void global_kernel(
    const float* __restrict__ u, const float* __restrict__ Wu,
    const float* __restrict__ bu, float* __restrict__ out)
{
    __shared__ float sin_[D_GLOB + D_HID];  // 192
    int g = blockIdx.x;
    int j = threadIdx.x;  // 0..63
    float cnt = fmaxf(g_counts[g], 1.0f);
    sin_[j] = u[g * D_GLOB + j];
    sin_[D_GLOB + j]      = g_pooled[g * D_HID + j] / cnt;
    sin_[D_GLOB + 64 + j] = g_pooled[g * D_HID + 64 + j] / cnt;
    __syncthreads();
    float acc = bu[j];
    #pragma unroll 8
    for (int k = 0; k < D_GLOB + D_HID; k++)
        acc = fmaf(sin_[k], Wu[k * D_GLOB + j], acc);
    out[g * D_GLOB + j] = fmaxf(acc, 0.0f);
}

// ---------------------------------------------------------------------------
extern "C" void kernel_launch(void* const* d_in, const int* in_sizes, int n_in,
                              void* d_out, int out_size)
{
    const float* x    = (const float*)d_in[0];
    const int*   eidx = (const int*)  d_in[1];
    const float* ea   = (const float*)d_in[2];
    const float* u    = (const float*)d_in[3];
    const int*   batch= (const int*)  d_in[4];
    const float* We1  = (const float*)d_in[5];
    const float* be1  = (const float*)d_in[6];
    const float* We2  = (const float*)d_in[7];
    const float* be2  = (const float*)d_in[8];
    const float* Wg   = (const float*)d_in[9];
    const float* bg   = (const float*)d_in[10];
    const float* Wn   = (const float*)d_in[11];
    const float* bn   = (const float*)d_in[12];
    const float* Wu   = (const float*)d_in[13];
    const float* bu   = (const float*)d_in[14];

    float* out   = (float*)d_out;
    float* u_new = out;                          // [512, 64]
    float* xw    = out + N_GRAPHS * D_GLOB;      // [50000, 128]

    zero_kernel<<<1024, 256>>>();
    edge_kernel<<<N_EDGES / TE, 256>>>(x, eidx, ea, We1, be1, We2, be2);
    node_kernel<<<(N_NODES + TE - 1) / TE, 256>>>(x, Wg, bg, Wn, bn, batch, xw);
    global_kernel<<<N_GRAPHS, 64>>>(u, Wu, bu, u_new);
}

// round 3
// speedup vs baseline: 2.2278x; 2.2278x over previous
#include <cuda_runtime.h>
#include <cuda_fp16.h>
#include <math.h>
#include <stdint.h>

#define N_NODES 50000
#define N_EDGES 800000
#define N_GRAPHS 512
#define D_IN 128
#define D_EDGE 32
#define D_HID 128
#define D_GLOB 64
#define K1 288              /* 2*D_IN + D_EDGE */

#define TILE_M 128
#define TILES_PER_CTA 5
#define EDGE_GRID (N_EDGES / (TILE_M * TILES_PER_CTA))  /* 1250 */

#define A_STRIDE 296        /* halves; 592B rows -> conflict-free ldmatrix */
#define H_STRIDE 136        /* halves; 272B rows -> conflict-free ldmatrix */

// ---- scratch (device globals; allocation forbidden) ----
__device__ float  g_agg[N_NODES * D_HID];      // 25.6 MB
__device__ float  g_pooled[N_GRAPHS * D_HID];
__device__ float  g_counts[N_GRAPHS];
// weights, fp16, prebuilt SMEM image: byte(k,n) = k*256 + (((n>>3)^(k&7))*16) + (n&7)*2
__device__ __half g_B1h[K1 * D_HID];           // We1
__device__ __half g_B2h[D_HID * D_HID];        // We2

// ---- dynamic SMEM layout (bytes) ----
#define SMEM_SRC  0                     /* 128 i32 */
#define SMEM_DST  512
#define SMEM_BE1  1024                  /* 128 f32 */
#define SMEM_BE2  1536
#define SMEM_A    2048                  /* 128 x 296 halves = 75776 */
#define SMEM_H    (SMEM_A + 75776)      /* 77824: 128 x 136 halves = 34816 */
#define SMEM_B1   (SMEM_H + 34816)      /* 112640: 288 x 256B = 73728 */
#define SMEM_B2   (SMEM_B1 + 73728)     /* 186368: 128 x 256B = 32768 */
#define SMEM_EDGE_TOTAL (SMEM_B2 + 32768)  /* 219136 */

// ============================ PTX helpers ===================================
__device__ __forceinline__ uint32_t smem_u32(const void* p) {
    uint32_t a;
    asm("{ .reg .u64 t; cvta.to.shared.u64 t, %1; cvt.u32.u64 %0, t; }" : "=r"(a) : "l"(p));
    return a;
}
__device__ __forceinline__ void ldm_x4(uint32_t* r, uint32_t addr) {
    asm volatile("ldmatrix.sync.aligned.m8n8.x4.shared.b16 {%0,%1,%2,%3}, [%4];"
                 : "=r"(r[0]), "=r"(r[1]), "=r"(r[2]), "=r"(r[3]) : "r"(addr));
}
__device__ __forceinline__ void ldm_x4_t(uint32_t* r, uint32_t addr) {
    asm volatile("ldmatrix.sync.aligned.m8n8.x4.trans.shared.b16 {%0,%1,%2,%3}, [%4];"
                 : "=r"(r[0]), "=r"(r[1]), "=r"(r[2]), "=r"(r[3]) : "r"(addr));
}
__device__ __forceinline__ void mma16816(float* c, const uint32_t* a, uint32_t b0, uint32_t b1) {
    asm volatile(
        "mma.sync.aligned.m16n8k16.row.col.f32.f16.f16.f32 "
        "{%0,%1,%2,%3}, {%4,%5,%6,%7}, {%8,%9}, {%0,%1,%2,%3};"
        : "+f"(c[0]), "+f"(c[1]), "+f"(c[2]), "+f"(c[3])
        : "r"(a[0]), "r"(a[1]), "r"(a[2]), "r"(a[3]), "r"(b0), "r"(b1));
}
__device__ __forceinline__ void red_add_v2(float* p, float a, float b) {
    asm volatile("red.global.add.v2.f32 [%0], {%1, %2};" :: "l"(p), "f"(a), "f"(b) : "memory");
}
__device__ __forceinline__ uint32_t h2_bits(__half2 h) {
    return *reinterpret_cast<uint32_t*>(&h);
}

// ============================================================================
__global__ void zero_kernel() {
    int idx = blockIdx.x * blockDim.x + threadIdx.x;
    int stride = gridDim.x * blockDim.x;
    for (int i = idx; i < N_NODES * D_HID; i += stride) g_agg[i] = 0.0f;
    for (int i = idx; i < N_GRAPHS * D_HID; i += stride) g_pooled[i] = 0.0f;
    for (int i = idx; i < N_GRAPHS; i += stride) g_counts[i] = 0.0f;
}

// Build fp16 weight images in the exact SMEM layout (copied verbatim later).
__global__ void prep_kernel(const float* __restrict__ We1, const float* __restrict__ We2) {
    int i = blockIdx.x * blockDim.x + threadIdx.x;
    if (i < K1 * D_HID) {
        int k = i >> 7, n = i & 127;
        uint32_t off = (uint32_t)k * 256 + (((n >> 3) ^ (k & 7)) * 16) + (n & 7) * 2;
        *(__half*)((char*)g_B1h + off) = __float2half_rn(We1[k * D_HID + n]);
    } else {
        int j = i - K1 * D_HID;
        if (j < D_HID * D_HID) {
            int k = j >> 7, n = j & 127;
            uint32_t off = (uint32_t)k * 256 + (((n >> 3) ^ (k & 7)) * 16) + (n & 7) * 2;
            *(__half*)((char*)g_B2h + off) = __float2half_rn(We2[k * D_HID + n]);
        }
    }
}

// ============================================================================
// Edge block via mma.sync fp16 (HMMA). 8 warps; warp w owns rows 16w..16w+15.
// ============================================================================
__global__ __launch_bounds__(256, 1) void edge_kernel(
    const float* __restrict__ x, const int* __restrict__ eidx,
    const float* __restrict__ ea,
    const float* __restrict__ be1, const float* __restrict__ be2)
{
    extern __shared__ char smem[];
    const uint32_t sb = smem_u32(smem);
    const int tid = threadIdx.x, wid = tid >> 5, lane = tid & 31;

    int*   sSrc = (int*)(smem + SMEM_SRC);
    int*   sDst = (int*)(smem + SMEM_DST);
    float* sBE1 = (float*)(smem + SMEM_BE1);
    float* sBE2 = (float*)(smem + SMEM_BE2);

    if (tid < D_HID) { sBE1[tid] = be1[tid]; sBE2[tid] = be2[tid]; }
    // stage weight images (verbatim copies)
    {
        const uint4* s1 = (const uint4*)g_B1h; uint4* d1 = (uint4*)(smem + SMEM_B1);
        #pragma unroll
        for (int i = 0; i < 18; i++) d1[tid + i * 256] = s1[tid + i * 256];
        const uint4* s2 = (const uint4*)g_B2h; uint4* d2 = (uint4*)(smem + SMEM_B2);
        #pragma unroll
        for (int i = 0; i < 8; i++) d2[tid + i * 256] = s2[tid + i * 256];
    }

    // lane-invariant address pieces
    const int lo15 = lane & 15;          // k row within 16
    const int hi   = lane >> 4;          // 0/1: second 8-col / +8-halves group
    const int lo7  = lane & 7;
    uint32_t bXor[8];
    #pragma unroll
    for (int p = 0; p < 8; p++) bXor[p] = (uint32_t)(((2 * p + hi) ^ lo7) * 16);

    const uint32_t aBase = sb + SMEM_A + ((16 * wid + lo15) * A_STRIDE + hi * 8) * 2;
    const uint32_t hBase = sb + SMEM_H + ((16 * wid + lo15) * H_STRIDE + hi * 8) * 2;
    const uint32_t b1Base = sb + SMEM_B1 + lo15 * 256;
    const uint32_t b2Base = sb + SMEM_B2 + lo15 * 256;

    const int rowLo = 16 * wid + (lane >> 2);   // output row for c0,c1
    const int colLo = (lane & 3) * 2;           // output col base (per ntile add nt*8)

    __syncthreads();

    for (int t = 0; t < TILES_PER_CTA; t++) {
        const int eBase = (blockIdx.x * TILES_PER_CTA + t) * TILE_M;
        if (tid < TILE_M) {
            sSrc[tid] = eidx[eBase + tid];
            sDst[tid] = eidx[N_EDGES + eBase + tid];
        }
        __syncthreads();

        // ---- gather A: 128 rows x 72 units of 4 fp16 ----
        #pragma unroll
        for (int it = 0; it < 36; it++) {
            int i = tid + it * 256;
            int e = i / 72, u = i - e * 72;
            int k0 = u * 4;
            float4 v;
            if (k0 < D_IN)          v = __ldg((const float4*)(x + (size_t)sSrc[e] * D_IN + k0));
            else if (k0 < 2 * D_IN) v = __ldg((const float4*)(x + (size_t)sDst[e] * D_IN + (k0 - D_IN)));
            else                    v = __ldg((const float4*)(ea + (size_t)(eBase + e) * D_EDGE + (k0 - 2 * D_IN)));
            __half2 h0 = __floats2half2_rn(v.x, v.y);
            __half2 h1 = __floats2half2_rn(v.z, v.w);
            *reinterpret_cast<uint2*>(smem + SMEM_A + (e * A_STRIDE + k0) * 2) =
                make_uint2(h2_bits(h0), h2_bits(h1));
        }
        __syncthreads();

        float c[16][4];
        #pragma unroll
        for (int nt = 0; nt < 16; nt++)
            #pragma unroll
            for (int j = 0; j < 4; j++) c[nt][j] = 0.0f;

        // ---- layer 1: K = 288 (18 k-steps) ----
        for (int ks = 0; ks < 18; ks++) {
            uint32_t a[4];
            ldm_x4(a, aBase + ks * 32);
            uint32_t bk = b1Base + ks * 4096;
            #pragma unroll
            for (int p = 0; p < 8; p++) {
                uint32_t b[4];
                ldm_x4_t(b, bk + bXor[p]);
                mma16816(c[2 * p + 0], a, b[0], b[1]);
                mma16816(c[2 * p + 1], a, b[2], b[3]);
            }
        }

        // ---- epilogue 1: bias + relu -> fp16 H (own rows only) ----
        #pragma unroll
        for (int nt = 0; nt < 16; nt++) {
            int col = nt * 8 + colLo;
            float2 bb = *(const float2*)(sBE1 + col);
            float v0 = fmaxf(c[nt][0] + bb.x, 0.f);
            float v1 = fmaxf(c[nt][1] + bb.y, 0.f);
            float v2 = fmaxf(c[nt][2] + bb.x, 0.f);
            float v3 = fmaxf(c[nt][3] + bb.y, 0.f);
            *(uint32_t*)(smem + SMEM_H + (rowLo * H_STRIDE + col) * 2) =
                h2_bits(__floats2half2_rn(v0, v1));
            *(uint32_t*)(smem + SMEM_H + ((rowLo + 8) * H_STRIDE + col) * 2) =
                h2_bits(__floats2half2_rn(v2, v3));
        }
        __syncwarp();

        #pragma unroll
        for (int nt = 0; nt < 16; nt++)
            #pragma unroll
            for (int j = 0; j < 4; j++) c[nt][j] = 0.0f;

        // ---- layer 2: K = 128 (8 k-steps) ----
        #pragma unroll
        for (int ks = 0; ks < 8; ks++) {
            uint32_t a[4];
            ldm_x4(a, hBase + ks * 32);
            uint32_t bk = b2Base + ks * 4096;
            #pragma unroll
            for (int p = 0; p < 8; p++) {
                uint32_t b[4];
                ldm_x4_t(b, bk + bXor[p]);
                mma16816(c[2 * p + 0], a, b[0], b[1]);
                mma16816(c[2 * p + 1], a, b[2], b[3]);
            }
        }

        // ---- epilogue 2: bias + relu -> vectorized scatter-add ----
        {
            float* dLo = g_agg + (size_t)sDst[rowLo] * D_HID;
            float* dHi = g_agg + (size_t)sDst[rowLo + 8] * D_HID;
            #pragma unroll
            for (int nt = 0; nt < 16; nt++) {
                int col = nt * 8 + colLo;
                float2 bb = *(const float2*)(sBE2 + col);
                red_add_v2(dLo + col, fmaxf(c[nt][0] + bb.x, 0.f), fmaxf(c[nt][1] + bb.y, 0.f));
                red_add_v2(dHi + col, fmaxf(c[nt][2] + bb.x, 0.f), fmaxf(c[nt][3] + bb.y, 0.f));
            }
        }
        __syncthreads();
    }
}

// ---------------------------------------------------------------------------
// Node block (fp32): gate/update MLPs + pooled sums. (Same as passing R0.)
// ---------------------------------------------------------------------------
#define TE 32
#define BK 32

__global__ __launch_bounds__(256) void node_kernel(
    const float* __restrict__ x,
    const float* __restrict__ Wg, const float* __restrict__ bg,
    const float* __restrict__ Wn, const float* __restrict__ bn,
    const int* __restrict__ batch, float* __restrict__ xw_out)
{
    __shared__ float sA[TE * (BK + 1)];
    __shared__ float sB[BK * D_HID];
    __shared__ float sG[TE * (D_HID + 4)];
    __shared__ float sBias[D_HID];
    __shared__ int   sBatch[TE];

    const int tid  = threadIdx.x;
    const int warp = tid >> 5;
    const int lane = tid & 31;
    const int nBase = blockIdx.x * TE;

    if (tid < TE) sBatch[tid] = (nBase + tid < N_NODES) ? batch[nBase + tid] : 0;

    for (int pass = 0; pass < 2; pass++) {
        const float* W = pass ? Wn : Wg;
        const float* b = pass ? bn : bg;
        if (tid < D_HID) sBias[tid] = b[tid];

        float acc[4][4] = {};
        for (int k0 = 0; k0 < 2 * D_HID; k0 += BK) {
            #pragma unroll
            for (int r = 0; r < 4; r++) {
                int idx = tid + r * 256;
                int e = idx >> 5, k = idx & 31;
                int gk = k0 + k;
                int n = nBase + e;
                float v = 0.0f;
                if (n < N_NODES)
                    v = (gk < D_IN) ? x[n * D_IN + gk]
                                    : g_agg[n * D_HID + (gk - D_IN)];
                sA[e * (BK + 1) + k] = v;
            }
            {
                const float4* s4 = (const float4*)(W + (size_t)k0 * D_HID);
                float4* d4 = (float4*)sB;
                #pragma unroll
                for (int r = 0; r < 4; r++) d4[tid + r * 256] = s4[tid + r * 256];
            }
            __syncthreads();
            #pragma unroll
            for (int kk = 0; kk < BK; kk++) {
                float a0 = sA[(warp * 4 + 0) * (BK + 1) + kk];
                float a1 = sA[(warp * 4 + 1) * (BK + 1) + kk];
                float a2 = sA[(warp * 4 + 2) * (BK + 1) + kk];
                float a3 = sA[(warp * 4 + 3) * (BK + 1) + kk];
                float4 bb = ((const float4*)(sB + kk * D_HID))[lane];
                acc[0][0] += a0 * bb.x; acc[0][1] += a0 * bb.y; acc[0][2] += a0 * bb.z; acc[0][3] += a0 * bb.w;
                acc[1][0] += a1 * bb.x; acc[1][1] += a1 * bb.y; acc[1][2] += a1 * bb.z; acc[1][3] += a1 * bb.w;
                acc[2][0] += a2 * bb.x; acc[2][1] += a2 * bb.y; acc[2][2] += a2 * bb.z; acc[2][3] += a2 * bb.w;
                acc[3][0] += a3 * bb.x; acc[3][1] += a3 * bb.y; acc[3][2] += a3 * bb.z; acc[3][3] += a3 * bb.w;
            }
            __syncthreads();
        }

        if (pass == 0) {
            #pragma unroll
            for (int i = 0; i < 4; i++) {
                int e = warp * 4 + i;
                int n = nBase + e;
                #pragma unroll
                for (int j = 0; j < 4; j++) {
                    int col = lane * 4 + j;
                    float g = 1.0f / (1.0f + expf(-(acc[i][j] + sBias[col])));
                    sG[e * (D_HID + 4) + col] = g;
                    if (n < N_NODES) xw_out[(size_t)n * D_HID + col] = g;
                }
            }
            if (lane == 0) {
                #pragma unroll
                for (int i = 0; i < 4; i++) {
                    int n = nBase + warp * 4 + i;
                    if (n < N_NODES) atomicAdd(&g_counts[sBatch[warp * 4 + i]], 1.0f);
                }
            }
            __syncthreads();
        } else {
            #pragma unroll
            for (int i = 0; i < 4; i++) {
                int e = warp * 4 + i;
                int n = nBase + e;
                int gidx = sBatch[e];
                #pragma unroll
                for (int j = 0; j < 4; j++) {
                    int col = lane * 4 + j;
                    float v = fmaxf(acc[i][j] + sBias[col], 0.0f);
                    float xn = sG[e * (D_HID + 4) + col] * v;
                    if (n < N_NODES) atomicAdd(&g_pooled[gidx * D_HID + col], xn);
                }
            }
        }
    }
}

// ---------------------------------------------------------------------------
__global__ __launch_bounds__(64) void global_kernel(
    const float* __restrict__ u, const float* __restrict__ Wu,
    const float* __restrict__ bu, float* __restrict__ out)
{
    __shared__ float sin_[D_GLOB + D_HID];
    int g = blockIdx.x;
    int j = threadIdx.x;
    float cnt = fmaxf(g_counts[g], 1.0f);
    sin_[j] = u[g * D_GLOB + j];
    sin_[D_GLOB + j]      = g_pooled[g * D_HID + j] / cnt;
    sin_[D_GLOB + 64 + j] = g_pooled[g * D_HID + 64 + j] / cnt;
    __syncthreads();
    float acc = bu[j];
    #pragma unroll 8
    for (int k = 0; k < D_GLOB + D_HID; k++)
        acc = fmaf(sin_[k], Wu[k * D_GLOB + j], acc);
    out[g * D_GLOB + j] = fmaxf(acc, 0.0f);
}

// ---------------------------------------------------------------------------
extern "C" void kernel_launch(void* const* d_in, const int* in_sizes, int n_in,
                              void* d_out, int out_size)
{
    const float* x    = (const float*)d_in[0];
    const int*   eidx = (const int*)  d_in[1];
    const float* ea   = (const float*)d_in[2];
    const float* u    = (const float*)d_in[3];
    const int*   batch= (const int*)  d_in[4];
    const float* We1  = (const float*)d_in[5];
    const float* be1  = (const float*)d_in[6];
    const float* We2  = (const float*)d_in[7];
    const float* be2  = (const float*)d_in[8];
    const float* Wg   = (const float*)d_in[9];
    const float* bg   = (const float*)d_in[10];
    const float* Wn   = (const float*)d_in[11];
    const float* bn   = (const float*)d_in[12];
    const float* Wu   = (const float*)d_in[13];
    const float* bu   = (const float*)d_in[14];

    float* out   = (float*)d_out;
    float* u_new = out;                          // [512, 64]
    float* xw    = out + N_GRAPHS * D_GLOB;      // [50000, 128]

    cudaFuncSetAttribute(edge_kernel, cudaFuncAttributeMaxDynamicSharedMemorySize,
                         SMEM_EDGE_TOTAL);

    zero_kernel<<<1024, 256>>>();
    prep_kernel<<<(K1 * D_HID + D_HID * D_HID + 255) / 256, 256>>>(We1, We2);
    edge_kernel<<<EDGE_GRID, 256, SMEM_EDGE_TOTAL>>>(x, eidx, ea, be1, be2);
    node_kernel<<<(N_NODES + TE - 1) / TE, 256>>>(x, Wg, bg, Wn, bn, batch, xw);
    global_kernel<<<N_GRAPHS, 64>>>(u, Wu, bu, u_new);
}

// round 5
// speedup vs baseline: 3.5819x; 1.6078x over previous
#include <cuda_runtime.h>
#include <cuda_fp16.h>
#include <math.h>
#include <stdint.h>

#define N_NODES 50000
#define N_EDGES 800000
#define N_GRAPHS 512
#define D_IN 128
#define D_EDGE 32
#define D_HID 128
#define D_GLOB 64
#define K1 288              /* 2*D_IN + D_EDGE */

#define TILE_M 64
#define TILES_PER_CTA 5
#define EDGE_GRID (N_EDGES / (TILE_M * TILES_PER_CTA))  /* 2500 */

#define A_STRIDE 296        /* halves */
#define H_STRIDE 136        /* halves */
#define SAF_STRIDE 132      /* f32 epilogue staging stride */

// ---- scratch (device globals; allocation forbidden) ----
__device__ float  g_agg[N_NODES * D_HID];
__device__ float  g_pooled[N_GRAPHS * D_HID];
__device__ float  g_counts[N_GRAPHS];
// fp16 weight images, SMEM layout: byte(k,n) = k*256 + (((n>>3)^(k&7))*16) + (n&7)*2
__device__ __half g_B1h[K1 * D_HID];        // We1  (288x128)
__device__ __half g_B2h[D_HID * D_HID];     // We2  (128x128)
__device__ __half g_Bgh[2 * D_HID * D_HID]; // Wg   (256x128)
__device__ __half g_Bnh[2 * D_HID * D_HID]; // Wn   (256x128)

// ---- edge kernel dynamic SMEM layout (bytes) ----
#define E_SRC   0                      /* 64 i32 */
#define E_DST   256
#define E_BE1   512                    /* 128 f32 */
#define E_BE2   1024
#define E_A     1536                   /* 64 x 296 halves = 37888 */
#define E_H     (E_A + 37888)          /* 64 x 136 halves = 17408 */
#define E_W     (E_H + 17408)          /* 36864 (max weight chunk) */
#define E_TOTAL (E_W + 36864)          /* 93696 */

// ---- node kernel dynamic SMEM layout ----
#define N_BG    0
#define N_BN    512
#define N_A     1024                   /* 64 x 296 halves = 37888 */
#define N_W     (N_A + 37888)
#define N_TOTAL (N_W + 65536)          /* 104448 */

// ============================ PTX helpers ===================================
__device__ __forceinline__ uint32_t smem_u32(const void* p) {
    uint32_t a;
    asm("{ .reg .u64 t; cvta.to.shared.u64 t, %1; cvt.u32.u64 %0, t; }" : "=r"(a) : "l"(p));
    return a;
}
__device__ __forceinline__ void ldm_x4(uint32_t* r, uint32_t addr) {
    asm volatile("ldmatrix.sync.aligned.m8n8.x4.shared.b16 {%0,%1,%2,%3}, [%4];"
                 : "=r"(r[0]), "=r"(r[1]), "=r"(r[2]), "=r"(r[3]) : "r"(addr));
}
__device__ __forceinline__ void ldm_x4_t(uint32_t* r, uint32_t addr) {
    asm volatile("ldmatrix.sync.aligned.m8n8.x4.trans.shared.b16 {%0,%1,%2,%3}, [%4];"
                 : "=r"(r[0]), "=r"(r[1]), "=r"(r[2]), "=r"(r[3]) : "r"(addr));
}
__device__ __forceinline__ void mma16816(float* c, const uint32_t* a, uint32_t b0, uint32_t b1) {
    asm volatile(
        "mma.sync.aligned.m16n8k16.row.col.f32.f16.f16.f32 "
        "{%0,%1,%2,%3}, {%4,%5,%6,%7}, {%8,%9}, {%0,%1,%2,%3};"
        : "+f"(c[0]), "+f"(c[1]), "+f"(c[2]), "+f"(c[3])
        : "r"(a[0]), "r"(a[1]), "r"(a[2]), "r"(a[3]), "r"(b0), "r"(b1));
}
__device__ __forceinline__ void red_add_v4(float* p, float a, float b, float c, float d) {
    asm volatile("red.global.add.v4.f32 [%0], {%1, %2, %3, %4};"
                 :: "l"(p), "f"(a), "f"(b), "f"(c), "f"(d) : "memory");
}
__device__ __forceinline__ void red_add_v2(float* p, float a, float b) {
    asm volatile("red.global.add.v2.f32 [%0], {%1, %2};" :: "l"(p), "f"(a), "f"(b) : "memory");
}
__device__ __forceinline__ uint32_t h2_bits(__half2 h) {
    return *reinterpret_cast<uint32_t*>(&h);
}

// ============================================================================
__global__ void zero_kernel() {
    int idx = blockIdx.x * blockDim.x + threadIdx.x;
    int stride = gridDim.x * blockDim.x;
    float4 z = make_float4(0.f, 0.f, 0.f, 0.f);
    float4* a4 = (float4*)g_agg;
    for (int i = idx; i < N_NODES * D_HID / 4; i += stride) a4[i] = z;
    for (int i = idx; i < N_GRAPHS * D_HID; i += stride) g_pooled[i] = 0.0f;
    for (int i = idx; i < N_GRAPHS; i += stride) g_counts[i] = 0.0f;
}

__global__ void prep_kernel(const float* __restrict__ We1, const float* __restrict__ We2,
                            const float* __restrict__ Wg,  const float* __restrict__ Wn) {
    int i = blockIdx.x * blockDim.x + threadIdx.x;
    int n = i & 127;
    if (i < K1 * D_HID) {
        int k = i >> 7;
        uint32_t off = (uint32_t)k * 256 + (((n >> 3) ^ (k & 7)) * 16) + (n & 7) * 2;
        *(__half*)((char*)g_B1h + off) = __float2half_rn(We1[k * D_HID + n]);
        return;
    }
    i -= K1 * D_HID;
    if (i < D_HID * D_HID) {
        int k = i >> 7; n = i & 127;
        uint32_t off = (uint32_t)k * 256 + (((n >> 3) ^ (k & 7)) * 16) + (n & 7) * 2;
        *(__half*)((char*)g_B2h + off) = __float2half_rn(We2[k * D_HID + n]);
        return;
    }
    i -= D_HID * D_HID;
    if (i < 2 * D_HID * D_HID) {
        int k = i >> 7; n = i & 127;
        uint32_t off = (uint32_t)k * 256 + (((n >> 3) ^ (k & 7)) * 16) + (n & 7) * 2;
        *(__half*)((char*)g_Bgh + off) = __float2half_rn(Wg[k * D_HID + n]);
        return;
    }
    i -= 2 * D_HID * D_HID;
    if (i < 2 * D_HID * D_HID) {
        int k = i >> 7; n = i & 127;
        uint32_t off = (uint32_t)k * 256 + (((n >> 3) ^ (k & 7)) * 16) + (n & 7) * 2;
        *(__half*)((char*)g_Bnh + off) = __float2half_rn(Wn[k * D_HID + n]);
    }
}

// ============================================================================
// Edge block: HMMA fp16, 64-edge tiles, streamed weights, 2 CTAs/SM.
// ============================================================================
__global__ __launch_bounds__(256, 2) void edge_kernel(
    const float* __restrict__ x, const int* __restrict__ eidx,
    const float* __restrict__ ea,
    const float* __restrict__ be1, const float* __restrict__ be2)
{
    extern __shared__ char smem[];
    const uint32_t sb = smem_u32(smem);
    const int tid = threadIdx.x, wid = tid >> 5, lane = tid & 31;
    const int wm = wid & 3, wn = wid >> 2;

    int*   sSrc = (int*)(smem + E_SRC);
    int*   sDst = (int*)(smem + E_DST);
    float* sBE1 = (float*)(smem + E_BE1);
    float* sBE2 = (float*)(smem + E_BE2);
    float* sAf  = (float*)(smem + E_A);

    if (tid < D_HID) { sBE1[tid] = be1[tid]; sBE2[tid] = be2[tid]; }

    const int lo15 = lane & 15;
    const int hi   = lane >> 4;
    const int lo7  = lane & 7;
    uint32_t bXor[4];
    #pragma unroll
    for (int p = 0; p < 4; p++) bXor[p] = (uint32_t)(((wn * 8 + 2 * p + hi) ^ lo7) * 16);

    const uint32_t aBase = sb + E_A + ((16 * wm + lo15) * A_STRIDE + hi * 8) * 2;
    const uint32_t hBase = sb + E_H + ((16 * wm + lo15) * H_STRIDE + hi * 8) * 2;
    const uint32_t wBase = sb + E_W + lo15 * 256;

    const int rowLo = 16 * wm + (lane >> 2);
    const int colLo = wn * 64 + (lane & 3) * 2;

    for (int t = 0; t < TILES_PER_CTA; t++) {
        const int eBase = (blockIdx.x * TILES_PER_CTA + t) * TILE_M;
        __syncthreads();   // prev tile's readers of sSrc/sDst/sAf are done

        if (tid < TILE_M)            sSrc[tid] = eidx[eBase + tid];
        else if (tid < 2 * TILE_M)   sDst[tid - TILE_M] = eidx[N_EDGES + eBase + tid - TILE_M];
        __syncthreads();   // indices visible to ALL threads before gather

        // gather A: 64 rows x 72 float4 units
        #pragma unroll
        for (int it = 0; it < 18; it++) {
            int i = tid + it * 256;
            int e = i / 72, u = i - e * 72;
            int k0 = u * 4;
            float4 v;
            if (k0 < D_IN)          v = __ldg((const float4*)(x + (size_t)sSrc[e] * D_IN + k0));
            else if (k0 < 2 * D_IN) v = __ldg((const float4*)(x + (size_t)sDst[e] * D_IN + (k0 - D_IN)));
            else                    v = __ldg((const float4*)(ea + (size_t)(eBase + e) * D_EDGE + (k0 - 2 * D_IN)));
            __half2 h0 = __floats2half2_rn(v.x, v.y);
            __half2 h1 = __floats2half2_rn(v.z, v.w);
            *reinterpret_cast<uint2*>(smem + E_A + (e * A_STRIDE + k0) * 2) =
                make_uint2(h2_bits(h0), h2_bits(h1));
        }
        // stage B1 first half (ksteps 0..8)
        {
            const uint4* s = (const uint4*)g_B1h; uint4* d = (uint4*)(smem + E_W);
            #pragma unroll
            for (int i = 0; i < 9; i++) d[tid + i * 256] = s[tid + i * 256];
        }
        __syncthreads();

        float c[8][4];
        #pragma unroll
        for (int nt = 0; nt < 8; nt++)
            #pragma unroll
            for (int j = 0; j < 4; j++) c[nt][j] = 0.0f;

        // layer 1 first half
        #pragma unroll
        for (int ks = 0; ks < 9; ks++) {
            uint32_t a[4];
            ldm_x4(a, aBase + ks * 32);
            uint32_t bk = wBase + ks * 4096;
            #pragma unroll
            for (int p = 0; p < 4; p++) {
                uint32_t b[4];
                ldm_x4_t(b, bk + bXor[p]);
                mma16816(c[2 * p + 0], a, b[0], b[1]);
                mma16816(c[2 * p + 1], a, b[2], b[3]);
            }
        }
        __syncthreads();
        {
            const uint4* s = (const uint4*)g_B1h + 2304; uint4* d = (uint4*)(smem + E_W);
            #pragma unroll
            for (int i = 0; i < 9; i++) d[tid + i * 256] = s[tid + i * 256];
        }
        __syncthreads();
        // layer 1 second half
        #pragma unroll
        for (int ks = 0; ks < 9; ks++) {
            uint32_t a[4];
            ldm_x4(a, aBase + (9 + ks) * 32);
            uint32_t bk = wBase + ks * 4096;
            #pragma unroll
            for (int p = 0; p < 4; p++) {
                uint32_t b[4];
                ldm_x4_t(b, bk + bXor[p]);
                mma16816(c[2 * p + 0], a, b[0], b[1]);
                mma16816(c[2 * p + 1], a, b[2], b[3]);
            }
        }
        __syncthreads();

        // epilogue 1 (bias+relu -> fp16 H) + stage B2
        #pragma unroll
        for (int nt = 0; nt < 8; nt++) {
            int col = nt * 8 + colLo;
            float2 bb = *(const float2*)(sBE1 + col);
            float v0 = fmaxf(c[nt][0] + bb.x, 0.f);
            float v1 = fmaxf(c[nt][1] + bb.y, 0.f);
            float v2 = fmaxf(c[nt][2] + bb.x, 0.f);
            float v3 = fmaxf(c[nt][3] + bb.y, 0.f);
            *(uint32_t*)(smem + E_H + (rowLo * H_STRIDE + col) * 2) =
                h2_bits(__floats2half2_rn(v0, v1));
            *(uint32_t*)(smem + E_H + ((rowLo + 8) * H_STRIDE + col) * 2) =
                h2_bits(__floats2half2_rn(v2, v3));
        }
        {
            const uint4* s = (const uint4*)g_B2h; uint4* d = (uint4*)(smem + E_W);
            #pragma unroll
            for (int i = 0; i < 8; i++) d[tid + i * 256] = s[tid + i * 256];
        }
        __syncthreads();

        #pragma unroll
        for (int nt = 0; nt < 8; nt++)
            #pragma unroll
            for (int j = 0; j < 4; j++) c[nt][j] = 0.0f;

        // layer 2: K = 128
        #pragma unroll
        for (int ks = 0; ks < 8; ks++) {
            uint32_t a[4];
            ldm_x4(a, hBase + ks * 32);
            uint32_t bk = wBase + ks * 4096;
            #pragma unroll
            for (int p = 0; p < 4; p++) {
                uint32_t b[4];
                ldm_x4_t(b, bk + bXor[p]);
                mma16816(c[2 * p + 0], a, b[0], b[1]);
                mma16816(c[2 * p + 1], a, b[2], b[3]);
            }
        }

        // epilogue 2: bias+relu -> f32 staging -> v4 scatter
        #pragma unroll
        for (int nt = 0; nt < 8; nt++) {
            int col = nt * 8 + colLo;
            float2 bb = *(const float2*)(sBE2 + col);
            sAf[rowLo * SAF_STRIDE + col]           = fmaxf(c[nt][0] + bb.x, 0.f);
            sAf[rowLo * SAF_STRIDE + col + 1]       = fmaxf(c[nt][1] + bb.y, 0.f);
            sAf[(rowLo + 8) * SAF_STRIDE + col]     = fmaxf(c[nt][2] + bb.x, 0.f);
            sAf[(rowLo + 8) * SAF_STRIDE + col + 1] = fmaxf(c[nt][3] + bb.y, 0.f);
        }
        __syncthreads();
        #pragma unroll
        for (int i = 0; i < 8; i++) {
            int v = tid + i * 256;          // 2048 v4 slots
            int row = v >> 5, c4 = v & 31;
            float4 val = *(const float4*)(sAf + row * SAF_STRIDE + c4 * 4);
            red_add_v4(g_agg + (size_t)sDst[row] * D_HID + c4 * 4, val.x, val.y, val.z, val.w);
        }
    }
}

// ============================================================================
// Node block: HMMA fp16. A = [x | agg] (64 nodes x 256), two GEMMs (Wg, Wn).
// ============================================================================
__global__ __launch_bounds__(256, 2) void node_kernel(
    const float* __restrict__ x,
    const float* __restrict__ bg, const float* __restrict__ bn,
    const int* __restrict__ batch, float* __restrict__ xw_out)
{
    extern __shared__ char smem[];
    const uint32_t sb = smem_u32(smem);
    const int tid = threadIdx.x, wid = tid >> 5, lane = tid & 31;
    const int wm = wid & 3, wn = wid >> 2;
    const int nBase = blockIdx.x * TILE_M;

    float* sBG = (float*)(smem + N_BG);
    float* sBN = (float*)(smem + N_BN);
    if (tid < D_HID) { sBG[tid] = bg[tid]; sBN[tid] = bn[tid]; }

    const int lo15 = lane & 15;
    const int hi   = lane >> 4;
    const int lo7  = lane & 7;
    uint32_t bXor[4];
    #pragma unroll
    for (int p = 0; p < 4; p++) bXor[p] = (uint32_t)(((wn * 8 + 2 * p + hi) ^ lo7) * 16);

    const uint32_t aBase = sb + N_A + ((16 * wm + lo15) * A_STRIDE + hi * 8) * 2;
    const uint32_t wBase = sb + N_W + lo15 * 256;

    const int rowLo = 16 * wm + (lane >> 2);
    const int rowHi = rowLo + 8;
    const int colLo = wn * 64 + (lane & 3) * 2;
    const int nLo = nBase + rowLo, nHi = nBase + rowHi;
    const int bLo = batch[min(nLo, N_NODES - 1)];
    const int bHi = batch[min(nHi, N_NODES - 1)];

    // build A: 64 rows x 64 float4 units (k 0..255)
    #pragma unroll
    for (int it = 0; it < 16; it++) {
        int i = tid + it * 256;
        int row = i >> 6, u = i & 63;
        int k0 = u * 4;
        int n = min(nBase + row, N_NODES - 1);
        float4 v = (k0 < D_IN)
            ? __ldg((const float4*)(x + (size_t)n * D_IN + k0))
            : *(const float4*)(g_agg + (size_t)n * D_HID + (k0 - D_IN));
        __half2 h0 = __floats2half2_rn(v.x, v.y);
        __half2 h1 = __floats2half2_rn(v.z, v.w);
        *reinterpret_cast<uint2*>(smem + N_A + (row * A_STRIDE + k0) * 2) =
            make_uint2(h2_bits(h0), h2_bits(h1));
    }
    // stage Wg
    {
        const uint4* s = (const uint4*)g_Bgh; uint4* d = (uint4*)(smem + N_W);
        #pragma unroll
        for (int i = 0; i < 16; i++) d[tid + i * 256] = s[tid + i * 256];
    }
    __syncthreads();

    float c[8][4];
    #pragma unroll
    for (int nt = 0; nt < 8; nt++)
        #pragma unroll
        for (int j = 0; j < 4; j++) c[nt][j] = 0.0f;

    #pragma unroll
    for (int ks = 0; ks < 16; ks++) {
        uint32_t a[4];
        ldm_x4(a, aBase + ks * 32);
        uint32_t bk = wBase + ks * 4096;
        #pragma unroll
        for (int p = 0; p < 4; p++) {
            uint32_t b[4];
            ldm_x4_t(b, bk + bXor[p]);
            mma16816(c[2 * p + 0], a, b[0], b[1]);
            mma16816(c[2 * p + 1], a, b[2], b[3]);
        }
    }

    // gate epilogue: sigmoid -> xw_out + keep in regs
    float gate[8][4];
    #pragma unroll
    for (int nt = 0; nt < 8; nt++) {
        int col = nt * 8 + colLo;
        float2 bb = *(const float2*)(sBG + col);
        gate[nt][0] = 1.0f / (1.0f + __expf(-(c[nt][0] + bb.x)));
        gate[nt][1] = 1.0f / (1.0f + __expf(-(c[nt][1] + bb.y)));
        gate[nt][2] = 1.0f / (1.0f + __expf(-(c[nt][2] + bb.x)));
        gate[nt][3] = 1.0f / (1.0f + __expf(-(c[nt][3] + bb.y)));
        if (nLo < N_NODES)
            *(float2*)(xw_out + (size_t)nLo * D_HID + col) = make_float2(gate[nt][0], gate[nt][1]);
        if (nHi < N_NODES)
            *(float2*)(xw_out + (size_t)nHi * D_HID + col) = make_float2(gate[nt][2], gate[nt][3]);
    }
    if (wn == 0 && (lane & 3) == 0) {
        if (nLo < N_NODES) atomicAdd(&g_counts[bLo], 1.0f);
        if (nHi < N_NODES) atomicAdd(&g_counts[bHi], 1.0f);
    }

    __syncthreads();
    {
        const uint4* s = (const uint4*)g_Bnh; uint4* d = (uint4*)(smem + N_W);
        #pragma unroll
        for (int i = 0; i < 16; i++) d[tid + i * 256] = s[tid + i * 256];
    }
    __syncthreads();

    #pragma unroll
    for (int nt = 0; nt < 8; nt++)
        #pragma unroll
        for (int j = 0; j < 4; j++) c[nt][j] = 0.0f;

    #pragma unroll
    for (int ks = 0; ks < 16; ks++) {
        uint32_t a[4];
        ldm_x4(a, aBase + ks * 32);
        uint32_t bk = wBase + ks * 4096;
        #pragma unroll
        for (int p = 0; p < 4; p++) {
            uint32_t b[4];
            ldm_x4_t(b, bk + bXor[p]);
            mma16816(c[2 * p + 0], a, b[0], b[1]);
            mma16816(c[2 * p + 1], a, b[2], b[3]);
        }
    }

    // x_new epilogue -> pooled atomics
    #pragma unroll
    for (int nt = 0; nt < 8; nt++) {
        int col = nt * 8 + colLo;
        float2 bb = *(const float2*)(sBN + col);
        float x0 = gate[nt][0] * fmaxf(c[nt][0] + bb.x, 0.f);
        float x1 = gate[nt][1] * fmaxf(c[nt][1] + bb.y, 0.f);
        float x2 = gate[nt][2] * fmaxf(c[nt][2] + bb.x, 0.f);
        float x3 = gate[nt][3] * fmaxf(c[nt][3] + bb.y, 0.f);
        if (nLo < N_NODES) red_add_v2(g_pooled + (size_t)bLo * D_HID + col, x0, x1);
        if (nHi < N_NODES) red_add_v2(g_pooled + (size_t)bHi * D_HID + col, x2, x3);
    }
}

// ---------------------------------------------------------------------------
__global__ __launch_bounds__(64) void global_kernel(
    const float* __restrict__ u, const float* __restrict__ Wu,
    const float* __restrict__ bu, float* __restrict__ out)
{
    __shared__ float sin_[D_GLOB + D_HID];
    int g = blockIdx.x;
    int j = threadIdx.x;
    float cnt = fmaxf(g_counts[g], 1.0f);
    sin_[j] = u[g * D_GLOB + j];
    sin_[D_GLOB + j]      = g_pooled[g * D_HID + j] / cnt;
    sin_[D_GLOB + 64 + j] = g_pooled[g * D_HID + 64 + j] / cnt;
    __syncthreads();
    float acc = bu[j];
    #pragma unroll 8
    for (int k = 0; k < D_GLOB + D_HID; k++)
        acc = fmaf(sin_[k], Wu[k * D_GLOB + j], acc);
    out[g * D_GLOB + j] = fmaxf(acc, 0.0f);
}

// ---------------------------------------------------------------------------
extern "C" void kernel_launch(void* const* d_in, const int* in_sizes, int n_in,
                              void* d_out, int out_size)
{
    const float* x    = (const float*)d_in[0];
    const int*   eidx = (const int*)  d_in[1];
    const float* ea   = (const float*)d_in[2];
    const float* u    = (const float*)d_in[3];
    const int*   batch= (const int*)  d_in[4];
    const float* We1  = (const float*)d_in[5];
    const float* be1  = (const float*)d_in[6];
    const float* We2  = (const float*)d_in[7];
    const float* be2  = (const float*)d_in[8];
    const float* Wg   = (const float*)d_in[9];
    const float* bg   = (const float*)d_in[10];
    const float* Wn   = (const float*)d_in[11];
    const float* bn   = (const float*)d_in[12];
    const float* Wu   = (const float*)d_in[13];
    const float* bu   = (const float*)d_in[14];

    float* out   = (float*)d_out;
    float* u_new = out;                          // [512, 64]
    float* xw    = out + N_GRAPHS * D_GLOB;      // [50000, 128]

    cudaFuncSetAttribute(edge_kernel, cudaFuncAttributeMaxDynamicSharedMemorySize, E_TOTAL);
    cudaFuncSetAttribute(node_kernel, cudaFuncAttributeMaxDynamicSharedMemorySize, N_TOTAL);

    zero_kernel<<<2048, 256>>>();
    int prep_elems = K1 * D_HID + D_HID * D_HID + 4 * D_HID * D_HID;
    prep_kernel<<<(prep_elems + 255) / 256, 256>>>(We1, We2, Wg, Wn);
    edge_kernel<<<EDGE_GRID, 256, E_TOTAL>>>(x, eidx, ea, be1, be2);
    node_kernel<<<(N_NODES + TILE_M - 1) / TILE_M, 256, N_TOTAL>>>(x, bg, bn, batch, xw);
    global_kernel<<<N_GRAPHS, 64>>>(u, Wu, bu, u_new);
}

// round 6
// speedup vs baseline: 4.8378x; 1.3506x over previous
#include <cuda_runtime.h>
#include <cuda_fp16.h>
#include <math.h>
#include <stdint.h>

#define N_NODES 50000
#define N_EDGES 800000
#define N_GRAPHS 512
#define D_IN 128
#define D_EDGE 32
#define D_HID 128
#define D_GLOB 64
#define K1 288

#define TILE_M 64
#define NT (N_EDGES / TILE_M)      /* 12500 tiles */
#define EDGE_GRID 148

#define A_STRIDE 296               /* halves: 592 B rows */
#define H_STRIDE 136               /* halves: 272 B rows */
#define STG_STRIDE 68              /* f32:    272 B rows */

// ---- scratch (device globals; allocation forbidden) ----
__device__ float  g_agg[N_NODES * D_HID];
__device__ float  g_pooled[N_GRAPHS * D_HID];
__device__ float  g_counts[N_GRAPHS];
__device__ __half g_xh[N_NODES * D_IN];       // fp16 copy of x
__device__ __half g_eah[N_EDGES * D_EDGE];    // fp16 copy of edge_attr
// fp16 weight images, SMEM layout: byte(k,n) = k*256 + (((n>>3)^(k&7))*16) + (n&7)*2
__device__ __half g_B1h[K1 * D_HID];
__device__ __half g_B2h[D_HID * D_HID];
__device__ __half g_Bgh[2 * D_HID * D_HID];
__device__ __half g_Bnh[2 * D_HID * D_HID];

// ---- edge kernel dynamic SMEM layout (bytes) ----
#define E_IDX   0                          /* 2 bufs x 128 ints = 1024 */
#define E_BE1   1024
#define E_BE2   1536
#define E_A     2048                       /* 2 x 64 x 592 = 75776 */
#define E_H     (E_A + 75776)              /* 77824: 17408 (H / f32 staging) */
#define E_W1    (E_H + 17408)              /* 95232: 73728 */
#define E_W2    (E_W1 + 73728)             /* 168960: 32768 */
#define E_TOTAL (E_W2 + 32768)             /* 201728 */

// ---- node kernel dynamic SMEM layout ----
#define N_BG    0
#define N_BN    512
#define N_A     1024
#define N_W     (N_A + 37888)
#define N_TOTAL (N_W + 65536)

// ============================ PTX helpers ===================================
__device__ __forceinline__ uint32_t smem_u32(const void* p) {
    uint32_t a;
    asm("{ .reg .u64 t; cvta.to.shared.u64 t, %1; cvt.u32.u64 %0, t; }" : "=r"(a) : "l"(p));
    return a;
}
__device__ __forceinline__ void ldm_x4(uint32_t* r, uint32_t addr) {
    asm volatile("ldmatrix.sync.aligned.m8n8.x4.shared.b16 {%0,%1,%2,%3}, [%4];"
                 : "=r"(r[0]), "=r"(r[1]), "=r"(r[2]), "=r"(r[3]) : "r"(addr));
}
__device__ __forceinline__ void ldm_x4_t(uint32_t* r, uint32_t addr) {
    asm volatile("ldmatrix.sync.aligned.m8n8.x4.trans.shared.b16 {%0,%1,%2,%3}, [%4];"
                 : "=r"(r[0]), "=r"(r[1]), "=r"(r[2]), "=r"(r[3]) : "r"(addr));
}
__device__ __forceinline__ void mma16816(float* c, const uint32_t* a, uint32_t b0, uint32_t b1) {
    asm volatile(
        "mma.sync.aligned.m16n8k16.row.col.f32.f16.f16.f32 "
        "{%0,%1,%2,%3}, {%4,%5,%6,%7}, {%8,%9}, {%0,%1,%2,%3};"
        : "+f"(c[0]), "+f"(c[1]), "+f"(c[2]), "+f"(c[3])
        : "r"(a[0]), "r"(a[1]), "r"(a[2]), "r"(a[3]), "r"(b0), "r"(b1));
}
__device__ __forceinline__ void red_add_v4(float* p, float a, float b, float c, float d) {
    asm volatile("red.global.add.v4.f32 [%0], {%1, %2, %3, %4};"
                 :: "l"(p), "f"(a), "f"(b), "f"(c), "f"(d) : "memory");
}
__device__ __forceinline__ void red_add_v2(float* p, float a, float b) {
    asm volatile("red.global.add.v2.f32 [%0], {%1, %2};" :: "l"(p), "f"(a), "f"(b) : "memory");
}
__device__ __forceinline__ void cpa16(uint32_t dst, const void* src) {
    asm volatile("cp.async.cg.shared.global [%0], [%1], 16;" :: "r"(dst), "l"(src) : "memory");
}
#define CPA_COMMIT() asm volatile("cp.async.commit_group;" ::: "memory")
#define CPA_WAIT0()  asm volatile("cp.async.wait_group 0;" ::: "memory")
__device__ __forceinline__ uint32_t h2_bits(__half2 h) {
    return *reinterpret_cast<uint32_t*>(&h);
}

// ============================================================================
__global__ void zero_kernel() {
    int idx = blockIdx.x * blockDim.x + threadIdx.x;
    int stride = gridDim.x * blockDim.x;
    float4 z = make_float4(0.f, 0.f, 0.f, 0.f);
    float4* a4 = (float4*)g_agg;
    for (int i = idx; i < N_NODES * D_HID / 4; i += stride) a4[i] = z;
    for (int i = idx; i < N_GRAPHS * D_HID; i += stride) g_pooled[i] = 0.0f;
    for (int i = idx; i < N_GRAPHS; i += stride) g_counts[i] = 0.0f;
}

// Convert x / edge_attr to fp16 (vectorized)
__global__ void prep_xe(const float* __restrict__ x, const float* __restrict__ ea) {
    int idx = blockIdx.x * blockDim.x + threadIdx.x;
    int stride = gridDim.x * blockDim.x;
    const int NX = N_NODES * D_IN / 4, NE = N_EDGES * D_EDGE / 4;
    for (int i = idx; i < NX; i += stride) {
        float4 v = __ldg((const float4*)x + i);
        __half2 h0 = __floats2half2_rn(v.x, v.y), h1 = __floats2half2_rn(v.z, v.w);
        *((uint2*)g_xh + i) = make_uint2(h2_bits(h0), h2_bits(h1));
    }
    for (int i = idx; i < NE; i += stride) {
        float4 v = __ldg((const float4*)ea + i);
        __half2 h0 = __floats2half2_rn(v.x, v.y), h1 = __floats2half2_rn(v.z, v.w);
        *((uint2*)g_eah + i) = make_uint2(h2_bits(h0), h2_bits(h1));
    }
}

__global__ void prep_w(const float* __restrict__ We1, const float* __restrict__ We2,
                       const float* __restrict__ Wg,  const float* __restrict__ Wn) {
    int i = blockIdx.x * blockDim.x + threadIdx.x;
    int n = i & 127;
    if (i < K1 * D_HID) {
        int k = i >> 7;
        uint32_t off = (uint32_t)k * 256 + (((n >> 3) ^ (k & 7)) * 16) + (n & 7) * 2;
        *(__half*)((char*)g_B1h + off) = __float2half_rn(We1[k * D_HID + n]);
        return;
    }
    i -= K1 * D_HID;
    if (i < D_HID * D_HID) {
        int k = i >> 7; n = i & 127;
        uint32_t off = (uint32_t)k * 256 + (((n >> 3) ^ (k & 7)) * 16) + (n & 7) * 2;
        *(__half*)((char*)g_B2h + off) = __float2half_rn(We2[k * D_HID + n]);
        return;
    }
    i -= D_HID * D_HID;
    if (i < 2 * D_HID * D_HID) {
        int k = i >> 7; n = i & 127;
        uint32_t off = (uint32_t)k * 256 + (((n >> 3) ^ (k & 7)) * 16) + (n & 7) * 2;
        *(__half*)((char*)g_Bgh + off) = __float2half_rn(Wg[k * D_HID + n]);
        return;
    }
    i -= 2 * D_HID * D_HID;
    if (i < 2 * D_HID * D_HID) {
        int k = i >> 7; n = i & 127;
        uint32_t off = (uint32_t)k * 256 + (((n >> 3) ^ (k & 7)) * 16) + (n & 7) * 2;
        *(__half*)((char*)g_Bnh + off) = __float2half_rn(Wn[k * D_HID + n]);
    }
}

// ============================================================================
// Edge block: persistent CTAs, resident weights, cp.async double-buffered A.
// ============================================================================
__global__ __launch_bounds__(256, 1) void edge_kernel(
    const int* __restrict__ eidx,
    const float* __restrict__ be1, const float* __restrict__ be2)
{
    extern __shared__ char smem[];
    const uint32_t sb = smem_u32(smem);
    const int tid = threadIdx.x, wid = tid >> 5, lane = tid & 31;
    const int wm = wid & 3, wn = wid >> 2;

    int*   sIdx = (int*)(smem + E_IDX);    // buf pb: src = +pb*128, dst = +pb*128+64
    float* sBE1 = (float*)(smem + E_BE1);
    float* sBE2 = (float*)(smem + E_BE2);
    float* sStg = (float*)(smem + E_H);

    if (tid < D_HID) { sBE1[tid] = be1[tid]; sBE2[tid] = be2[tid]; }

    // resident weights
    {
        const uint4* s1 = (const uint4*)g_B1h; uint4* d1 = (uint4*)(smem + E_W1);
        #pragma unroll
        for (int i = 0; i < 18; i++) d1[tid + i * 256] = s1[tid + i * 256];
        const uint4* s2 = (const uint4*)g_B2h; uint4* d2 = (uint4*)(smem + E_W2);
        #pragma unroll
        for (int i = 0; i < 8; i++) d2[tid + i * 256] = s2[tid + i * 256];
    }

    const int lo15 = lane & 15;
    const int hi   = lane >> 4;
    const int lo7  = lane & 7;
    uint32_t bXor[4];
    #pragma unroll
    for (int p = 0; p < 4; p++) bXor[p] = (uint32_t)(((wn * 8 + 2 * p + hi) ^ lo7) * 16);

    const uint32_t aOff  = ((16 * wm + lo15) * A_STRIDE + hi * 8) * 2;
    const uint32_t hBase = sb + E_H + ((16 * wm + lo15) * H_STRIDE + hi * 8) * 2;
    const uint32_t w1Base = sb + E_W1 + lo15 * 256;
    const uint32_t w2Base = sb + E_W2 + lo15 * 256;

    const int rowLo = 16 * wm + (lane >> 2);
    const int colLo = wn * 64 + (lane & 3) * 2;

    int t = blockIdx.x;
    int pb = 0;
    // prologue: idx(t) into buf 0
    if (tid < TILE_M)            sIdx[tid] = eidx[t * TILE_M + tid];
    else if (tid < 2 * TILE_M)   sIdx[tid] = eidx[N_EDGES + t * TILE_M + (tid - TILE_M)];
    __syncthreads();
    // issue gather(t) into A buf 0
    {
        const int* sS = sIdx, *sD = sIdx + 64;
        #pragma unroll
        for (int it = 0; it < 9; it++) {
            int i = tid + it * 256;
            int row = i / 36, u = i - row * 36;
            const void* src;
            if (u < 16)      src = g_xh + (size_t)sS[row] * D_IN + u * 8;
            else if (u < 32) src = g_xh + (size_t)sD[row] * D_IN + (u - 16) * 8;
            else             src = g_eah + (size_t)(t * TILE_M + row) * D_EDGE + (u - 32) * 8;
            cpa16(sb + E_A + row * 592 + u * 16, src);
        }
        CPA_COMMIT();
    }

    for (; t < NT; t += EDGE_GRID, pb ^= 1) {
        const int tn = t + EDGE_GRID;
        // load idx(tn) into buf pb^1
        if (tn < NT) {
            if (tid < TILE_M)          sIdx[(pb ^ 1) * 128 + tid] = eidx[tn * TILE_M + tid];
            else if (tid < 2 * TILE_M) sIdx[(pb ^ 1) * 128 + tid] =
                                           eidx[N_EDGES + tn * TILE_M + (tid - TILE_M)];
        }
        CPA_WAIT0();
        __syncthreads();   // A(t) ready, idx(tn) visible, staging free

        // issue gather(tn) into buf pb^1 (overlaps MMAs below)
        if (tn < NT) {
            const int* sS = sIdx + (pb ^ 1) * 128, *sD = sS + 64;
            uint32_t abuf = sb + E_A + (pb ^ 1) * 37888;
            #pragma unroll
            for (int it = 0; it < 9; it++) {
                int i = tid + it * 256;
                int row = i / 36, u = i - row * 36;
                const void* src;
                if (u < 16)      src = g_xh + (size_t)sS[row] * D_IN + u * 8;
                else if (u < 32) src = g_xh + (size_t)sD[row] * D_IN + (u - 16) * 8;
                else             src = g_eah + (size_t)(tn * TILE_M + row) * D_EDGE + (u - 32) * 8;
                cpa16(abuf + row * 592 + u * 16, src);
            }
            CPA_COMMIT();
        }

        const uint32_t aBase = sb + E_A + pb * 37888 + aOff;
        const int* sDstP = sIdx + pb * 128 + 64;

        float c[8][4];
        #pragma unroll
        for (int nt = 0; nt < 8; nt++)
            #pragma unroll
            for (int j = 0; j < 4; j++) c[nt][j] = 0.0f;

        // ---- layer 1: K = 288 ----
        #pragma unroll
        for (int ks = 0; ks < 18; ks++) {
            uint32_t a[4];
            ldm_x4(a, aBase + ks * 32);
            uint32_t bk = w1Base + ks * 4096;
            #pragma unroll
            for (int p = 0; p < 4; p++) {
                uint32_t b[4];
                ldm_x4_t(b, bk + bXor[p]);
                mma16816(c[2 * p + 0], a, b[0], b[1]);
                mma16816(c[2 * p + 1], a, b[2], b[3]);
            }
        }

        // epilogue 1: bias+relu -> fp16 H
        #pragma unroll
        for (int nt = 0; nt < 8; nt++) {
            int col = nt * 8 + colLo;
            float2 bb = *(const float2*)(sBE1 + col);
            float v0 = fmaxf(c[nt][0] + bb.x, 0.f);
            float v1 = fmaxf(c[nt][1] + bb.y, 0.f);
            float v2 = fmaxf(c[nt][2] + bb.x, 0.f);
            float v3 = fmaxf(c[nt][3] + bb.y, 0.f);
            *(uint32_t*)(smem + E_H + (rowLo * H_STRIDE + col) * 2) =
                h2_bits(__floats2half2_rn(v0, v1));
            *(uint32_t*)(smem + E_H + ((rowLo + 8) * H_STRIDE + col) * 2) =
                h2_bits(__floats2half2_rn(v2, v3));
        }
        __syncthreads();   // H cross-warp visibility (wn pairs share rows)

        #pragma unroll
        for (int nt = 0; nt < 8; nt++)
            #pragma unroll
            for (int j = 0; j < 4; j++) c[nt][j] = 0.0f;

        // ---- layer 2: K = 128 ----
        #pragma unroll
        for (int ks = 0; ks < 8; ks++) {
            uint32_t a[4];
            ldm_x4(a, hBase + ks * 32);
            uint32_t bk = w2Base + ks * 4096;
            #pragma unroll
            for (int p = 0; p < 4; p++) {
                uint32_t b[4];
                ldm_x4_t(b, bk + bXor[p]);
                mma16816(c[2 * p + 0], a, b[0], b[1]);
                mma16816(c[2 * p + 1], a, b[2], b[3]);
            }
        }
        __syncthreads();   // all MMA2 H reads done before staging overwrites H

        // epilogue 2: two 64-col passes through f32 staging -> v4 scatter
        #pragma unroll
        for (int p = 0; p < 2; p++) {
            if (wn == p) {
                #pragma unroll
                for (int nt = 0; nt < 8; nt++) {
                    int col = nt * 8 + colLo;
                    int cl = col & 63;
                    float2 bb = *(const float2*)(sBE2 + col);
                    *(float2*)(sStg + rowLo * STG_STRIDE + cl) =
                        make_float2(fmaxf(c[nt][0] + bb.x, 0.f), fmaxf(c[nt][1] + bb.y, 0.f));
                    *(float2*)(sStg + (rowLo + 8) * STG_STRIDE + cl) =
                        make_float2(fmaxf(c[nt][2] + bb.x, 0.f), fmaxf(c[nt][3] + bb.y, 0.f));
                }
            }
            __syncthreads();
            #pragma unroll
            for (int i = 0; i < 4; i++) {
                int v = tid + i * 256;       // 1024 v4 slots
                int row = v >> 4, c4 = v & 15;
                float4 val = *(const float4*)(sStg + row * STG_STRIDE + c4 * 4);
                red_add_v4(g_agg + (size_t)sDstP[row] * D_HID + p * 64 + c4 * 4,
                           val.x, val.y, val.z, val.w);
            }
            __syncthreads();
        }
    }
}

// ============================================================================
// Node block: HMMA fp16 (unchanged from R5, passing).
// ============================================================================
__global__ __launch_bounds__(256, 2) void node_kernel(
    const float* __restrict__ x,
    const float* __restrict__ bg, const float* __restrict__ bn,
    const int* __restrict__ batch, float* __restrict__ xw_out)
{
    extern __shared__ char smem[];
    const uint32_t sb = smem_u32(smem);
    const int tid = threadIdx.x, wid = tid >> 5, lane = tid & 31;
    const int wm = wid & 3, wn = wid >> 2;
    const int nBase = blockIdx.x * TILE_M;

    float* sBG = (float*)(smem + N_BG);
    float* sBN = (float*)(smem + N_BN);
    if (tid < D_HID) { sBG[tid] = bg[tid]; sBN[tid] = bn[tid]; }

    const int lo15 = lane & 15;
    const int hi   = lane >> 4;
    const int lo7  = lane & 7;
    uint32_t bXor[4];
    #pragma unroll
    for (int p = 0; p < 4; p++) bXor[p] = (uint32_t)(((wn * 8 + 2 * p + hi) ^ lo7) * 16);

    const uint32_t aBase = sb + N_A + ((16 * wm + lo15) * A_STRIDE + hi * 8) * 2;
    const uint32_t wBase = sb + N_W + lo15 * 256;

    const int rowLo = 16 * wm + (lane >> 2);
    const int rowHi = rowLo + 8;
    const int colLo = wn * 64 + (lane & 3) * 2;
    const int nLo = nBase + rowLo, nHi = nBase + rowHi;
    const int bLo = batch[min(nLo, N_NODES - 1)];
    const int bHi = batch[min(nHi, N_NODES - 1)];

    #pragma unroll
    for (int it = 0; it < 16; it++) {
        int i = tid + it * 256;
        int row = i >> 6, u = i & 63;
        int k0 = u * 4;
        int n = min(nBase + row, N_NODES - 1);
        float4 v = (k0 < D_IN)
            ? __ldg((const float4*)(x + (size_t)n * D_IN + k0))
            : *(const float4*)(g_agg + (size_t)n * D_HID + (k0 - D_IN));
        __half2 h0 = __floats2half2_rn(v.x, v.y);
        __half2 h1 = __floats2half2_rn(v.z, v.w);
        *reinterpret_cast<uint2*>(smem + N_A + (row * A_STRIDE + k0) * 2) =
            make_uint2(h2_bits(h0), h2_bits(h1));
    }
    {
        const uint4* s = (const uint4*)g_Bgh; uint4* d = (uint4*)(smem + N_W);
        #pragma unroll
        for (int i = 0; i < 16; i++) d[tid + i * 256] = s[tid + i * 256];
    }
    __syncthreads();

    float c[8][4];
    #pragma unroll
    for (int nt = 0; nt < 8; nt++)
        #pragma unroll
        for (int j = 0; j < 4; j++) c[nt][j] = 0.0f;

    #pragma unroll
    for (int ks = 0; ks < 16; ks++) {
        uint32_t a[4];
        ldm_x4(a, aBase + ks * 32);
        uint32_t bk = wBase + ks * 4096;
        #pragma unroll
        for (int p = 0; p < 4; p++) {
            uint32_t b[4];
            ldm_x4_t(b, bk + bXor[p]);
            mma16816(c[2 * p + 0], a, b[0], b[1]);
            mma16816(c[2 * p + 1], a, b[2], b[3]);
        }
    }

    float gate[8][4];
    #pragma unroll
    for (int nt = 0; nt < 8; nt++) {
        int col = nt * 8 + colLo;
        float2 bb = *(const float2*)(sBG + col);
        gate[nt][0] = 1.0f / (1.0f + __expf(-(c[nt][0] + bb.x)));
        gate[nt][1] = 1.0f / (1.0f + __expf(-(c[nt][1] + bb.y)));
        gate[nt][2] = 1.0f / (1.0f + __expf(-(c[nt][2] + bb.x)));
        gate[nt][3] = 1.0f / (1.0f + __expf(-(c[nt][3] + bb.y)));
        if (nLo < N_NODES)
            *(float2*)(xw_out + (size_t)nLo * D_HID + col) = make_float2(gate[nt][0], gate[nt][1]);
        if (nHi < N_NODES)
            *(float2*)(xw_out + (size_t)nHi * D_HID + col) = make_float2(gate[nt][2], gate[nt][3]);
    }
    if (wn == 0 && (lane & 3) == 0) {
        if (nLo < N_NODES) atomicAdd(&g_counts[bLo], 1.0f);
        if (nHi < N_NODES) atomicAdd(&g_counts[bHi], 1.0f);
    }

    __syncthreads();
    {
        const uint4* s = (const uint4*)g_Bnh; uint4* d = (uint4*)(smem + N_W);
        #pragma unroll
        for (int i = 0; i < 16; i++) d[tid + i * 256] = s[tid + i * 256];
    }
    __syncthreads();

    #pragma unroll
    for (int nt = 0; nt < 8; nt++)
        #pragma unroll
        for (int j = 0; j < 4; j++) c[nt][j] = 0.0f;

    #pragma unroll
    for (int ks = 0; ks < 16; ks++) {
        uint32_t a[4];
        ldm_x4(a, aBase + ks * 32);
        uint32_t bk = wBase + ks * 4096;
        #pragma unroll
        for (int p = 0; p < 4; p++) {
            uint32_t b[4];
            ldm_x4_t(b, bk + bXor[p]);
            mma16816(c[2 * p + 0], a, b[0], b[1]);
            mma16816(c[2 * p + 1], a, b[2], b[3]);
        }
    }

    #pragma unroll
    for (int nt = 0; nt < 8; nt++) {
        int col = nt * 8 + colLo;
        float2 bb = *(const float2*)(sBN + col);
        float x0 = gate[nt][0] * fmaxf(c[nt][0] + bb.x, 0.f);
        float x1 = gate[nt][1] * fmaxf(c[nt][1] + bb.y, 0.f);
        float x2 = gate[nt][2] * fmaxf(c[nt][2] + bb.x, 0.f);
        float x3 = gate[nt][3] * fmaxf(c[nt][3] + bb.y, 0.f);
        if (nLo < N_NODES) red_add_v2(g_pooled + (size_t)bLo * D_HID + col, x0, x1);
        if (nHi < N_NODES) red_add_v2(g_pooled + (size_t)bHi * D_HID + col, x2, x3);
    }
}

// ---------------------------------------------------------------------------
__global__ __launch_bounds__(64) void global_kernel(
    const float* __restrict__ u, const float* __restrict__ Wu,
    const float* __restrict__ bu, float* __restrict__ out)
{
    __shared__ float sin_[D_GLOB + D_HID];
    int g = blockIdx.x;
    int j = threadIdx.x;
    float cnt = fmaxf(g_counts[g], 1.0f);
    sin_[j] = u[g * D_GLOB + j];
    sin_[D_GLOB + j]      = g_pooled[g * D_HID + j] / cnt;
    sin_[D_GLOB + 64 + j] = g_pooled[g * D_HID + 64 + j] / cnt;
    __syncthreads();
    float acc = bu[j];
    #pragma unroll 8
    for (int k = 0; k < D_GLOB + D_HID; k++)
        acc = fmaf(sin_[k], Wu[k * D_GLOB + j], acc);
    out[g * D_GLOB + j] = fmaxf(acc, 0.0f);
}

// ---------------------------------------------------------------------------
extern "C" void kernel_launch(void* const* d_in, const int* in_sizes, int n_in,
                              void* d_out, int out_size)
{
    const float* x    = (const float*)d_in[0];
    const int*   eidx = (const int*)  d_in[1];
    const float* ea   = (const float*)d_in[2];
    const float* u    = (const float*)d_in[3];
    const int*   batch= (const int*)  d_in[4];
    const float* We1  = (const float*)d_in[5];
    const float* be1  = (const float*)d_in[6];
    const float* We2  = (const float*)d_in[7];
    const float* be2  = (const float*)d_in[8];
    const float* Wg   = (const float*)d_in[9];
    const float* bg   = (const float*)d_in[10];
    const float* Wn   = (const float*)d_in[11];
    const float* bn   = (const float*)d_in[12];
    const float* Wu   = (const float*)d_in[13];
    const float* bu   = (const float*)d_in[14];

    float* out   = (float*)d_out;
    float* u_new = out;
    float* xw    = out + N_GRAPHS * D_GLOB;

    cudaFuncSetAttribute(edge_kernel, cudaFuncAttributeMaxDynamicSharedMemorySize, E_TOTAL);
    cudaFuncSetAttribute(node_kernel, cudaFuncAttributeMaxDynamicSharedMemorySize, N_TOTAL);

    zero_kernel<<<2048, 256>>>();
    prep_xe<<<2048, 256>>>(x, ea);
    int prep_elems = K1 * D_HID + D_HID * D_HID + 4 * D_HID * D_HID;
    prep_w<<<(prep_elems + 255) / 256, 256>>>(We1, We2, Wg, Wn);
    edge_kernel<<<EDGE_GRID, 256, E_TOTAL>>>(eidx, be1, be2);
    node_kernel<<<(N_NODES + TILE_M - 1) / TILE_M, 256, N_TOTAL>>>(x, bg, bn, batch, xw);
    global_kernel<<<N_GRAPHS, 64>>>(u, Wu, bu, u_new);
}

// round 7
// speedup vs baseline: 5.0478x; 1.0434x over previous
#include <cuda_runtime.h>
#include <cuda_fp16.h>
#include <math.h>
#include <stdint.h>

#define N_NODES 50000
#define N_EDGES 800000
#define N_GRAPHS 512
#define D_IN 128
#define D_EDGE 32
#define D_HID 128
#define D_GLOB 64
#define K1 288

#define TILE_M 64
#define NT (N_EDGES / TILE_M)      /* 12500 tiles */
#define EDGE_GRID 148
#define ETHREADS 512

#define A_STRIDE 296               /* halves: 592 B rows */
#define H_STRIDE 136               /* halves: 272 B rows */
#define STG_STRIDE 68              /* f32:    272 B rows */

// ---- scratch ----
__device__ float  g_agg[N_NODES * D_HID];
__device__ float  g_pooled[N_GRAPHS * D_HID];
__device__ float  g_counts[N_GRAPHS];
__device__ __half g_xh[N_NODES * D_IN];
__device__ __half g_eah[N_EDGES * D_EDGE];
// fp16 weight images: byte(k,n) = k*256 + (((n>>3)^(k&7))*16) + (n&7)*2
__device__ __half g_B1h[K1 * D_HID];
__device__ __half g_B2h[D_HID * D_HID];
__device__ __half g_Bgh[2 * D_HID * D_HID];
__device__ __half g_Bnh[2 * D_HID * D_HID];

// ---- edge kernel SMEM layout (bytes) ----
#define E_IDX   0                          /* 2 bufs x 128 ints */
#define E_BE1   1024
#define E_BE2   1536
#define E_A     2048                       /* 2 x 64 x 592 = 75776 */
#define E_H     (E_A + 75776)              /* 17408 (H / f32 staging) */
#define E_W1    (E_H + 17408)              /* 73728 */
#define E_W2    (E_W1 + 73728)             /* 32768 */
#define E_TOTAL (E_W2 + 32768)             /* 201728 */

// ---- node kernel SMEM layout ----
#define N_BG    0
#define N_BN    512
#define N_A     1024
#define N_W     (N_A + 37888)
#define N_TOTAL (N_W + 65536)

// ============================ PTX helpers ===================================
__device__ __forceinline__ uint32_t smem_u32(const void* p) {
    uint32_t a;
    asm("{ .reg .u64 t; cvta.to.shared.u64 t, %1; cvt.u32.u64 %0, t; }" : "=r"(a) : "l"(p));
    return a;
}
__device__ __forceinline__ void ldm_x4(uint32_t* r, uint32_t addr) {
    asm volatile("ldmatrix.sync.aligned.m8n8.x4.shared.b16 {%0,%1,%2,%3}, [%4];"
                 : "=r"(r[0]), "=r"(r[1]), "=r"(r[2]), "=r"(r[3]) : "r"(addr));
}
__device__ __forceinline__ void ldm_x4_t(uint32_t* r, uint32_t addr) {
    asm volatile("ldmatrix.sync.aligned.m8n8.x4.trans.shared.b16 {%0,%1,%2,%3}, [%4];"
                 : "=r"(r[0]), "=r"(r[1]), "=r"(r[2]), "=r"(r[3]) : "r"(addr));
}
__device__ __forceinline__ void mma16816(float* c, const uint32_t* a, uint32_t b0, uint32_t b1) {
    asm volatile(
        "mma.sync.aligned.m16n8k16.row.col.f32.f16.f16.f32 "
        "{%0,%1,%2,%3}, {%4,%5,%6,%7}, {%8,%9}, {%0,%1,%2,%3};"
        : "+f"(c[0]), "+f"(c[1]), "+f"(c[2]), "+f"(c[3])
        : "r"(a[0]), "r"(a[1]), "r"(a[2]), "r"(a[3]), "r"(b0), "r"(b1));
}
__device__ __forceinline__ void red_add_v4(float* p, float a, float b, float c, float d) {
    asm volatile("red.global.add.v4.f32 [%0], {%1, %2, %3, %4};"
                 :: "l"(p), "f"(a), "f"(b), "f"(c), "f"(d) : "memory");
}
__device__ __forceinline__ void red_add_v2(float* p, float a, float b) {
    asm volatile("red.global.add.v2.f32 [%0], {%1, %2};" :: "l"(p), "f"(a), "f"(b) : "memory");
}
__device__ __forceinline__ void cpa16(uint32_t dst, const void* src) {
    asm volatile("cp.async.cg.shared.global [%0], [%1], 16;" :: "r"(dst), "l"(src) : "memory");
}
#define CPA_COMMIT() asm volatile("cp.async.commit_group;" ::: "memory")
#define CPA_WAIT0()  asm volatile("cp.async.wait_group 0;" ::: "memory")
__device__ __forceinline__ uint32_t h2_bits(__half2 h) {
    return *reinterpret_cast<uint32_t*>(&h);
}

// ============================================================================
__global__ void zero_kernel() {
    int idx = blockIdx.x * blockDim.x + threadIdx.x;
    int stride = gridDim.x * blockDim.x;
    float4 z = make_float4(0.f, 0.f, 0.f, 0.f);
    float4* a4 = (float4*)g_agg;
    for (int i = idx; i < N_NODES * D_HID / 4; i += stride) a4[i] = z;
    for (int i = idx; i < N_GRAPHS * D_HID; i += stride) g_pooled[i] = 0.0f;
    for (int i = idx; i < N_GRAPHS; i += stride) g_counts[i] = 0.0f;
}

__global__ void prep_xe(const float* __restrict__ x, const float* __restrict__ ea) {
    int idx = blockIdx.x * blockDim.x + threadIdx.x;
    int stride = gridDim.x * blockDim.x;
    const int NX = N_NODES * D_IN / 4, NE = N_EDGES * D_EDGE / 4;
    for (int i = idx; i < NX; i += stride) {
        float4 v = __ldg((const float4*)x + i);
        __half2 h0 = __floats2half2_rn(v.x, v.y), h1 = __floats2half2_rn(v.z, v.w);
        *((uint2*)g_xh + i) = make_uint2(h2_bits(h0), h2_bits(h1));
    }
    for (int i = idx; i < NE; i += stride) {
        float4 v = __ldg((const float4*)ea + i);
        __half2 h0 = __floats2half2_rn(v.x, v.y), h1 = __floats2half2_rn(v.z, v.w);
        *((uint2*)g_eah + i) = make_uint2(h2_bits(h0), h2_bits(h1));
    }
}

__global__ void prep_w(const float* __restrict__ We1, const float* __restrict__ We2,
                       const float* __restrict__ Wg,  const float* __restrict__ Wn) {
    int i = blockIdx.x * blockDim.x + threadIdx.x;
    int n = i & 127;
    if (i < K1 * D_HID) {
        int k = i >> 7;
        uint32_t off = (uint32_t)k * 256 + (((n >> 3) ^ (k & 7)) * 16) + (n & 7) * 2;
        *(__half*)((char*)g_B1h + off) = __float2half_rn(We1[k * D_HID + n]);
        return;
    }
    i -= K1 * D_HID;
    if (i < D_HID * D_HID) {
        int k = i >> 7; n = i & 127;
        uint32_t off = (uint32_t)k * 256 + (((n >> 3) ^ (k & 7)) * 16) + (n & 7) * 2;
        *(__half*)((char*)g_B2h + off) = __float2half_rn(We2[k * D_HID + n]);
        return;
    }
    i -= D_HID * D_HID;
    if (i < 2 * D_HID * D_HID) {
        int k = i >> 7; n = i & 127;
        uint32_t off = (uint32_t)k * 256 + (((n >> 3) ^ (k & 7)) * 16) + (n & 7) * 2;
        *(__half*)((char*)g_Bgh + off) = __float2half_rn(Wg[k * D_HID + n]);
        return;
    }
    i -= 2 * D_HID * D_HID;
    if (i < 2 * D_HID * D_HID) {
        int k = i >> 7; n = i & 127;
        uint32_t off = (uint32_t)k * 256 + (((n >> 3) ^ (k & 7)) * 16) + (n & 7) * 2;
        *(__half*)((char*)g_Bnh + off) = __float2half_rn(Wn[k * D_HID + n]);
    }
}

// ============================================================================
// Edge block: persistent CTAs, 512 threads (4x4 warp grid), resident weights,
// cp.async double-buffered gather.
// Warp wm=wid&3 -> rows 16wm..16wm+15; wn=wid>>2 -> cols 32wn..32wn+31.
// ============================================================================
__global__ __launch_bounds__(ETHREADS, 1) void edge_kernel(
    const int* __restrict__ eidx,
    const float* __restrict__ be1, const float* __restrict__ be2)
{
    extern __shared__ char smem[];
    const uint32_t sb = smem_u32(smem);
    const int tid = threadIdx.x, wid = tid >> 5, lane = tid & 31;
    const int wm = wid & 3, wn = wid >> 2;

    int*   sIdx = (int*)(smem + E_IDX);
    float* sBE1 = (float*)(smem + E_BE1);
    float* sBE2 = (float*)(smem + E_BE2);
    float* sStg = (float*)(smem + E_H);

    if (tid < D_HID) { sBE1[tid] = be1[tid]; sBE2[tid] = be2[tid]; }

    // resident weights
    {
        const uint4* s1 = (const uint4*)g_B1h; uint4* d1 = (uint4*)(smem + E_W1);
        #pragma unroll
        for (int i = 0; i < 9; i++) d1[tid + i * 512] = s1[tid + i * 512];
        const uint4* s2 = (const uint4*)g_B2h; uint4* d2 = (uint4*)(smem + E_W2);
        #pragma unroll
        for (int i = 0; i < 4; i++) d2[tid + i * 512] = s2[tid + i * 512];
    }

    const int lo15 = lane & 15;
    const int hi   = lane >> 4;
    const int lo7  = lane & 7;
    uint32_t bXor[2];
    #pragma unroll
    for (int p = 0; p < 2; p++) bXor[p] = (uint32_t)(((wn * 4 + 2 * p + hi) ^ lo7) * 16);

    const uint32_t aOff   = ((16 * wm + lo15) * A_STRIDE + hi * 8) * 2;
    const uint32_t hBase  = sb + E_H + ((16 * wm + lo15) * H_STRIDE + hi * 8) * 2;
    const uint32_t w1Base = sb + E_W1 + lo15 * 256;
    const uint32_t w2Base = sb + E_W2 + lo15 * 256;

    const int rowLo = 16 * wm + (lane >> 2);
    const int colLo = wn * 32 + (lane & 3) * 2;

    int t = blockIdx.x;
    int pb = 0;
    if (tid < TILE_M)            sIdx[tid] = eidx[t * TILE_M + tid];
    else if (tid < 2 * TILE_M)   sIdx[tid] = eidx[N_EDGES + t * TILE_M + (tid - TILE_M)];
    __syncthreads();
    {
        const int* sS = sIdx, *sD = sIdx + 64;
        #pragma unroll
        for (int it = 0; it < 5; it++) {
            int i = tid + it * ETHREADS;
            if (i < 2304) {
                int row = i / 36, u = i - row * 36;
                const void* src;
                if (u < 16)      src = g_xh + (size_t)sS[row] * D_IN + u * 8;
                else if (u < 32) src = g_xh + (size_t)sD[row] * D_IN + (u - 16) * 8;
                else             src = g_eah + (size_t)(t * TILE_M + row) * D_EDGE + (u - 32) * 8;
                cpa16(sb + E_A + row * 592 + u * 16, src);
            }
        }
        CPA_COMMIT();
    }

    for (; t < NT; t += EDGE_GRID, pb ^= 1) {
        const int tn = t + EDGE_GRID;
        if (tn < NT) {
            if (tid < TILE_M)          sIdx[(pb ^ 1) * 128 + tid] = eidx[tn * TILE_M + tid];
            else if (tid < 2 * TILE_M) sIdx[(pb ^ 1) * 128 + tid] =
                                           eidx[N_EDGES + tn * TILE_M + (tid - TILE_M)];
        }
        CPA_WAIT0();
        __syncthreads();

        if (tn < NT) {
            const int* sS = sIdx + (pb ^ 1) * 128, *sD = sS + 64;
            uint32_t abuf = sb + E_A + (pb ^ 1) * 37888;
            #pragma unroll
            for (int it = 0; it < 5; it++) {
                int i = tid + it * ETHREADS;
                if (i < 2304) {
                    int row = i / 36, u = i - row * 36;
                    const void* src;
                    if (u < 16)      src = g_xh + (size_t)sS[row] * D_IN + u * 8;
                    else if (u < 32) src = g_xh + (size_t)sD[row] * D_IN + (u - 16) * 8;
                    else             src = g_eah + (size_t)(tn * TILE_M + row) * D_EDGE + (u - 32) * 8;
                    cpa16(abuf + row * 592 + u * 16, src);
                }
            }
            CPA_COMMIT();
        }

        const uint32_t aBase = sb + E_A + pb * 37888 + aOff;
        const int* sDstP = sIdx + pb * 128 + 64;

        float c[4][4];
        #pragma unroll
        for (int nt = 0; nt < 4; nt++)
            #pragma unroll
            for (int j = 0; j < 4; j++) c[nt][j] = 0.0f;

        // ---- layer 1: K = 288 ----
        #pragma unroll
        for (int ks = 0; ks < 18; ks++) {
            uint32_t a[4];
            ldm_x4(a, aBase + ks * 32);
            uint32_t bk = w1Base + ks * 4096;
            #pragma unroll
            for (int p = 0; p < 2; p++) {
                uint32_t b[4];
                ldm_x4_t(b, bk + bXor[p]);
                mma16816(c[2 * p + 0], a, b[0], b[1]);
                mma16816(c[2 * p + 1], a, b[2], b[3]);
            }
        }

        // epilogue 1: bias+relu -> fp16 H
        #pragma unroll
        for (int nt = 0; nt < 4; nt++) {
            int col = nt * 8 + colLo;
            float2 bb = *(const float2*)(sBE1 + col);
            float v0 = fmaxf(c[nt][0] + bb.x, 0.f);
            float v1 = fmaxf(c[nt][1] + bb.y, 0.f);
            float v2 = fmaxf(c[nt][2] + bb.x, 0.f);
            float v3 = fmaxf(c[nt][3] + bb.y, 0.f);
            *(uint32_t*)(smem + E_H + (rowLo * H_STRIDE + col) * 2) =
                h2_bits(__floats2half2_rn(v0, v1));
            *(uint32_t*)(smem + E_H + ((rowLo + 8) * H_STRIDE + col) * 2) =
                h2_bits(__floats2half2_rn(v2, v3));
        }
        __syncthreads();

        #pragma unroll
        for (int nt = 0; nt < 4; nt++)
            #pragma unroll
            for (int j = 0; j < 4; j++) c[nt][j] = 0.0f;

        // ---- layer 2: K = 128 ----
        #pragma unroll
        for (int ks = 0; ks < 8; ks++) {
            uint32_t a[4];
            ldm_x4(a, hBase + ks * 32);
            uint32_t bk = w2Base + ks * 4096;
            #pragma unroll
            for (int p = 0; p < 2; p++) {
                uint32_t b[4];
                ldm_x4_t(b, bk + bXor[p]);
                mma16816(c[2 * p + 0], a, b[0], b[1]);
                mma16816(c[2 * p + 1], a, b[2], b[3]);
            }
        }
        __syncthreads();   // H reads done before staging overwrites

        // epilogue 2: two 64-col passes through f32 staging -> v4 scatter
        #pragma unroll
        for (int p = 0; p < 2; p++) {
            if ((wn >> 1) == p) {
                #pragma unroll
                for (int nt = 0; nt < 4; nt++) {
                    int col = nt * 8 + colLo;
                    int cl = col & 63;
                    float2 bb = *(const float2*)(sBE2 + col);
                    *(float2*)(sStg + rowLo * STG_STRIDE + cl) =
                        make_float2(fmaxf(c[nt][0] + bb.x, 0.f), fmaxf(c[nt][1] + bb.y, 0.f));
                    *(float2*)(sStg + (rowLo + 8) * STG_STRIDE + cl) =
                        make_float2(fmaxf(c[nt][2] + bb.x, 0.f), fmaxf(c[nt][3] + bb.y, 0.f));
                }
            }
            __syncthreads();
            #pragma unroll
            for (int i = 0; i < 2; i++) {
                int v = tid + i * ETHREADS;      // 1024 v4 slots
                int row = v >> 4, c4 = v & 15;
                float4 val = *(const float4*)(sStg + row * STG_STRIDE + c4 * 4);
                red_add_v4(g_agg + (size_t)sDstP[row] * D_HID + p * 64 + c4 * 4,
                           val.x, val.y, val.z, val.w);
            }
            __syncthreads();
        }
    }
}

// ============================================================================
// Node block: HMMA fp16 (unchanged from R6, passing).
// ============================================================================
__global__ __launch_bounds__(256, 2) void node_kernel(
    const float* __restrict__ x,
    const float* __restrict__ bg, const float* __restrict__ bn,
    const int* __restrict__ batch, float* __restrict__ xw_out)
{
    extern __shared__ char smem[];
    const uint32_t sb = smem_u32(smem);
    const int tid = threadIdx.x, wid = tid >> 5, lane = tid & 31;
    const int wm = wid & 3, wn = wid >> 2;
    const int nBase = blockIdx.x * TILE_M;

    float* sBG = (float*)(smem + N_BG);
    float* sBN = (float*)(smem + N_BN);
    if (tid < D_HID) { sBG[tid] = bg[tid]; sBN[tid] = bn[tid]; }

    const int lo15 = lane & 15;
    const int hi   = lane >> 4;
    const int lo7  = lane & 7;
    uint32_t bXor[4];
    #pragma unroll
    for (int p = 0; p < 4; p++) bXor[p] = (uint32_t)(((wn * 8 + 2 * p + hi) ^ lo7) * 16);

    const uint32_t aBase = sb + N_A + ((16 * wm + lo15) * A_STRIDE + hi * 8) * 2;
    const uint32_t wBase = sb + N_W + lo15 * 256;

    const int rowLo = 16 * wm + (lane >> 2);
    const int rowHi = rowLo + 8;
    const int colLo = wn * 64 + (lane & 3) * 2;
    const int nLo = nBase + rowLo, nHi = nBase + rowHi;
    const int bLo = batch[min(nLo, N_NODES - 1)];
    const int bHi = batch[min(nHi, N_NODES - 1)];

    #pragma unroll
    for (int it = 0; it < 16; it++) {
        int i = tid + it * 256;
        int row = i >> 6, u = i & 63;
        int k0 = u * 4;
        int n = min(nBase + row, N_NODES - 1);
        float4 v = (k0 < D_IN)
            ? __ldg((const float4*)(x + (size_t)n * D_IN + k0))
            : *(const float4*)(g_agg + (size_t)n * D_HID + (k0 - D_IN));
        __half2 h0 = __floats2half2_rn(v.x, v.y);
        __half2 h1 = __floats2half2_rn(v.z, v.w);
        *reinterpret_cast<uint2*>(smem + N_A + (row * A_STRIDE + k0) * 2) =
            make_uint2(h2_bits(h0), h2_bits(h1));
    }
    {
        const uint4* s = (const uint4*)g_Bgh; uint4* d = (uint4*)(smem + N_W);
        #pragma unroll
        for (int i = 0; i < 16; i++) d[tid + i * 256] = s[tid + i * 256];
    }
    __syncthreads();

    float c[8][4];
    #pragma unroll
    for (int nt = 0; nt < 8; nt++)
        #pragma unroll
        for (int j = 0; j < 4; j++) c[nt][j] = 0.0f;

    #pragma unroll
    for (int ks = 0; ks < 16; ks++) {
        uint32_t a[4];
        ldm_x4(a, aBase + ks * 32);
        uint32_t bk = wBase + ks * 4096;
        #pragma unroll
        for (int p = 0; p < 4; p++) {
            uint32_t b[4];
            ldm_x4_t(b, bk + bXor[p]);
            mma16816(c[2 * p + 0], a, b[0], b[1]);
            mma16816(c[2 * p + 1], a, b[2], b[3]);
        }
    }

    float gate[8][4];
    #pragma unroll
    for (int nt = 0; nt < 8; nt++) {
        int col = nt * 8 + colLo;
        float2 bb = *(const float2*)(sBG + col);
        gate[nt][0] = 1.0f / (1.0f + __expf(-(c[nt][0] + bb.x)));
        gate[nt][1] = 1.0f / (1.0f + __expf(-(c[nt][1] + bb.y)));
        gate[nt][2] = 1.0f / (1.0f + __expf(-(c[nt][2] + bb.x)));
        gate[nt][3] = 1.0f / (1.0f + __expf(-(c[nt][3] + bb.y)));
        if (nLo < N_NODES)
            *(float2*)(xw_out + (size_t)nLo * D_HID + col) = make_float2(gate[nt][0], gate[nt][1]);
        if (nHi < N_NODES)
            *(float2*)(xw_out + (size_t)nHi * D_HID + col) = make_float2(gate[nt][2], gate[nt][3]);
    }
    if (wn == 0 && (lane & 3) == 0) {
        if (nLo < N_NODES) atomicAdd(&g_counts[bLo], 1.0f);
        if (nHi < N_NODES) atomicAdd(&g_counts[bHi], 1.0f);
    }

    __syncthreads();
    {
        const uint4* s = (const uint4*)g_Bnh; uint4* d = (uint4*)(smem + N_W);
        #pragma unroll
        for (int i = 0; i < 16; i++) d[tid + i * 256] = s[tid + i * 256];
    }
    __syncthreads();

    #pragma unroll
    for (int nt = 0; nt < 8; nt++)
        #pragma unroll
        for (int j = 0; j < 4; j++) c[nt][j] = 0.0f;

    #pragma unroll
    for (int ks = 0; ks < 16; ks++) {
        uint32_t a[4];
        ldm_x4(a, aBase + ks * 32);
        uint32_t bk = wBase + ks * 4096;
        #pragma unroll
        for (int p = 0; p < 4; p++) {
            uint32_t b[4];
            ldm_x4_t(b, bk + bXor[p]);
            mma16816(c[2 * p + 0], a, b[0], b[1]);
            mma16816(c[2 * p + 1], a, b[2], b[3]);
        }
    }

    #pragma unroll
    for (int nt = 0; nt < 8; nt++) {
        int col = nt * 8 + colLo;
        float2 bb = *(const float2*)(sBN + col);
        float x0 = gate[nt][0] * fmaxf(c[nt][0] + bb.x, 0.f);
        float x1 = gate[nt][1] * fmaxf(c[nt][1] + bb.y, 0.f);
        float x2 = gate[nt][2] * fmaxf(c[nt][2] + bb.x, 0.f);
        float x3 = gate[nt][3] * fmaxf(c[nt][3] + bb.y, 0.f);
        if (nLo < N_NODES) red_add_v2(g_pooled + (size_t)bLo * D_HID + col, x0, x1);
        if (nHi < N_NODES) red_add_v2(g_pooled + (size_t)bHi * D_HID + col, x2, x3);
    }
}

// ---------------------------------------------------------------------------
__global__ __launch_bounds__(64) void global_kernel(
    const float* __restrict__ u, const float* __restrict__ Wu,
    const float* __restrict__ bu, float* __restrict__ out)
{
    __shared__ float sin_[D_GLOB + D_HID];
    int g = blockIdx.x;
    int j = threadIdx.x;
    float cnt = fmaxf(g_counts[g], 1.0f);
    sin_[j] = u[g * D_GLOB + j];
    sin_[D_GLOB + j]      = g_pooled[g * D_HID + j] / cnt;
    sin_[D_GLOB + 64 + j] = g_pooled[g * D_HID + 64 + j] / cnt;
    __syncthreads();
    float acc = bu[j];
    #pragma unroll 8
    for (int k = 0; k < D_GLOB + D_HID; k++)
        acc = fmaf(sin_[k], Wu[k * D_GLOB + j], acc);
    out[g * D_GLOB + j] = fmaxf(acc, 0.0f);
}

// ---------------------------------------------------------------------------
extern "C" void kernel_launch(void* const* d_in, const int* in_sizes, int n_in,
                              void* d_out, int out_size)
{
    const float* x    = (const float*)d_in[0];
    const int*   eidx = (const int*)  d_in[1];
    const float* ea   = (const float*)d_in[2];
    const float* u    = (const float*)d_in[3];
    const int*   batch= (const int*)  d_in[4];
    const float* We1  = (const float*)d_in[5];
    const float* be1  = (const float*)d_in[6];
    const float* We2  = (const float*)d_in[7];
    const float* be2  = (const float*)d_in[8];
    const float* Wg   = (const float*)d_in[9];
    const float* bg   = (const float*)d_in[10];
    const float* Wn   = (const float*)d_in[11];
    const float* bn   = (const float*)d_in[12];
    const float* Wu   = (const float*)d_in[13];
    const float* bu   = (const float*)d_in[14];

    float* out   = (float*)d_out;
    float* u_new = out;
    float* xw    = out + N_GRAPHS * D_GLOB;

    cudaFuncSetAttribute(edge_kernel, cudaFuncAttributeMaxDynamicSharedMemorySize, E_TOTAL);
    cudaFuncSetAttribute(node_kernel, cudaFuncAttributeMaxDynamicSharedMemorySize, N_TOTAL);

    zero_kernel<<<2048, 256>>>();
    prep_xe<<<2048, 256>>>(x, ea);
    int prep_elems = K1 * D_HID + D_HID * D_HID + 4 * D_HID * D_HID;
    prep_w<<<(prep_elems + 255) / 256, 256>>>(We1, We2, Wg, Wn);
    edge_kernel<<<EDGE_GRID, ETHREADS, E_TOTAL>>>(eidx, be1, be2);
    node_kernel<<<(N_NODES + TILE_M - 1) / TILE_M, 256, N_TOTAL>>>(x, bg, bn, batch, xw);
    global_kernel<<<N_GRAPHS, 64>>>(u, Wu, bu, u_new);
}

// round 8
// speedup vs baseline: 5.8523x; 1.1594x over previous
#include <cuda_runtime.h>
#include <cuda_fp16.h>
#include <math.h>
#include <stdint.h>

#define N_NODES 50000
#define N_EDGES 800000
#define N_GRAPHS 512
#define D_IN 128
#define D_EDGE 32
#define D_HID 128
#define D_GLOB 64
#define K1 288

#define TILE_M 64                  /* node kernel tile */
#define TILE_E 128                 /* edge kernel tile */
#define NT2 (N_EDGES / TILE_E)     /* 6250 tiles */
#define EDGE_GRID 148
#define ETHREADS 512

#define A_STRIDE 296               /* halves: 592 B rows */
#define H_STRIDE 136               /* halves: 272 B rows */
#define STG_STRIDE 68              /* f32:    272 B rows */

// ---- scratch ----
__device__ float  g_agg[N_NODES * D_HID];
__device__ float  g_pooled[N_GRAPHS * D_HID];
__device__ float  g_counts[N_GRAPHS];
__device__ __half g_xh[N_NODES * D_IN];
__device__ __half g_eah[N_EDGES * D_EDGE];
// fp16 weight images: byte(k,n) = k*256 + (((n>>3)^(k&7))*16) + (n&7)*2
__device__ __half g_B1h[K1 * D_HID];
__device__ __half g_B2h[D_HID * D_HID];
__device__ __half g_Bgh[2 * D_HID * D_HID];
__device__ __half g_Bnh[2 * D_HID * D_HID];

// ---- edge kernel SMEM layout (bytes) ----
#define E_IDX   0                          /* 2 bufs x 256 ints = 2048 */
#define E_BE1   2048
#define E_BE2   2560
#define E_A     3072                       /* 128 x 592 = 75776 */
#define E_H     (E_A + 75776)              /* 78848: 128 x 272 = 34816 */
#define E_W1    (E_H + 34816)              /* 113664: 73728 */
#define E_W2    (E_W1 + 73728)             /* 187392: 32768 */
#define E_TOTAL (E_W2 + 32768)             /* 220160 */

// ---- node kernel SMEM layout ----
#define N_BG    0
#define N_BN    512
#define N_A     1024
#define N_W     (N_A + 37888)
#define N_TOTAL (N_W + 65536)

// ============================ PTX helpers ===================================
__device__ __forceinline__ uint32_t smem_u32(const void* p) {
    uint32_t a;
    asm("{ .reg .u64 t; cvta.to.shared.u64 t, %1; cvt.u32.u64 %0, t; }" : "=r"(a) : "l"(p));
    return a;
}
__device__ __forceinline__ void ldm_x4(uint32_t* r, uint32_t addr) {
    asm volatile("ldmatrix.sync.aligned.m8n8.x4.shared.b16 {%0,%1,%2,%3}, [%4];"
                 : "=r"(r[0]), "=r"(r[1]), "=r"(r[2]), "=r"(r[3]) : "r"(addr));
}
__device__ __forceinline__ void ldm_x4_t(uint32_t* r, uint32_t addr) {
    asm volatile("ldmatrix.sync.aligned.m8n8.x4.trans.shared.b16 {%0,%1,%2,%3}, [%4];"
                 : "=r"(r[0]), "=r"(r[1]), "=r"(r[2]), "=r"(r[3]) : "r"(addr));
}
__device__ __forceinline__ void mma16816(float* c, const uint32_t* a, uint32_t b0, uint32_t b1) {
    asm volatile(
        "mma.sync.aligned.m16n8k16.row.col.f32.f16.f16.f32 "
        "{%0,%1,%2,%3}, {%4,%5,%6,%7}, {%8,%9}, {%0,%1,%2,%3};"
        : "+f"(c[0]), "+f"(c[1]), "+f"(c[2]), "+f"(c[3])
        : "r"(a[0]), "r"(a[1]), "r"(a[2]), "r"(a[3]), "r"(b0), "r"(b1));
}
__device__ __forceinline__ void red_add_v4(float* p, float a, float b, float c, float d) {
    asm volatile("red.global.add.v4.f32 [%0], {%1, %2, %3, %4};"
                 :: "l"(p), "f"(a), "f"(b), "f"(c), "f"(d) : "memory");
}
__device__ __forceinline__ void red_add_v2(float* p, float a, float b) {
    asm volatile("red.global.add.v2.f32 [%0], {%1, %2};" :: "l"(p), "f"(a), "f"(b) : "memory");
}
__device__ __forceinline__ void cpa16(uint32_t dst, const void* src) {
    asm volatile("cp.async.cg.shared.global [%0], [%1], 16;" :: "r"(dst), "l"(src) : "memory");
}
#define CPA_COMMIT() asm volatile("cp.async.commit_group;" ::: "memory")
#define CPA_WAIT0()  asm volatile("cp.async.wait_group 0;" ::: "memory")
__device__ __forceinline__ uint32_t h2_bits(__half2 h) {
    return *reinterpret_cast<uint32_t*>(&h);
}

// ============================================================================
__global__ void zero_kernel() {
    int idx = blockIdx.x * blockDim.x + threadIdx.x;
    int stride = gridDim.x * blockDim.x;
    float4 z = make_float4(0.f, 0.f, 0.f, 0.f);
    float4* a4 = (float4*)g_agg;
    for (int i = idx; i < N_NODES * D_HID / 4; i += stride) a4[i] = z;
    for (int i = idx; i < N_GRAPHS * D_HID; i += stride) g_pooled[i] = 0.0f;
    for (int i = idx; i < N_GRAPHS; i += stride) g_counts[i] = 0.0f;
}

__global__ void prep_xe(const float* __restrict__ x, const float* __restrict__ ea) {
    int idx = blockIdx.x * blockDim.x + threadIdx.x;
    int stride = gridDim.x * blockDim.x;
    const int NX = N_NODES * D_IN / 4, NE = N_EDGES * D_EDGE / 4;
    for (int i = idx; i < NX; i += stride) {
        float4 v = __ldg((const float4*)x + i);
        __half2 h0 = __floats2half2_rn(v.x, v.y), h1 = __floats2half2_rn(v.z, v.w);
        *((uint2*)g_xh + i) = make_uint2(h2_bits(h0), h2_bits(h1));
    }
    for (int i = idx; i < NE; i += stride) {
        float4 v = __ldg((const float4*)ea + i);
        __half2 h0 = __floats2half2_rn(v.x, v.y), h1 = __floats2half2_rn(v.z, v.w);
        *((uint2*)g_eah + i) = make_uint2(h2_bits(h0), h2_bits(h1));
    }
}

__global__ void prep_w(const float* __restrict__ We1, const float* __restrict__ We2,
                       const float* __restrict__ Wg,  const float* __restrict__ Wn) {
    int i = blockIdx.x * blockDim.x + threadIdx.x;
    int n = i & 127;
    if (i < K1 * D_HID) {
        int k = i >> 7;
        uint32_t off = (uint32_t)k * 256 + (((n >> 3) ^ (k & 7)) * 16) + (n & 7) * 2;
        *(__half*)((char*)g_B1h + off) = __float2half_rn(We1[k * D_HID + n]);
        return;
    }
    i -= K1 * D_HID;
    if (i < D_HID * D_HID) {
        int k = i >> 7; n = i & 127;
        uint32_t off = (uint32_t)k * 256 + (((n >> 3) ^ (k & 7)) * 16) + (n & 7) * 2;
        *(__half*)((char*)g_B2h + off) = __float2half_rn(We2[k * D_HID + n]);
        return;
    }
    i -= D_HID * D_HID;
    if (i < 2 * D_HID * D_HID) {
        int k = i >> 7; n = i & 127;
        uint32_t off = (uint32_t)k * 256 + (((n >> 3) ^ (k & 7)) * 16) + (n & 7) * 2;
        *(__half*)((char*)g_Bgh + off) = __float2half_rn(Wg[k * D_HID + n]);
        return;
    }
    i -= 2 * D_HID * D_HID;
    if (i < 2 * D_HID * D_HID) {
        int k = i >> 7; n = i & 127;
        uint32_t off = (uint32_t)k * 256 + (((n >> 3) ^ (k & 7)) * 16) + (n & 7) * 2;
        *(__half*)((char*)g_Bnh + off) = __float2half_rn(Wn[k * D_HID + n]);
    }
}

// ============================================================================
// Edge block: persistent CTAs, 128-edge tiles, 4x4 warp grid of 32x32 tiles,
// resident weights, single A buffer with gather(t+1) overlapped past layer 1.
// ============================================================================
__global__ __launch_bounds__(ETHREADS, 1) void edge_kernel(
    const int* __restrict__ eidx,
    const float* __restrict__ be1, const float* __restrict__ be2)
{
    extern __shared__ char smem[];
    const uint32_t sb = smem_u32(smem);
    const int tid = threadIdx.x, wid = tid >> 5, lane = tid & 31;
    const int wm = wid & 3, wn = wid >> 2;

    int*   sIdx = (int*)(smem + E_IDX);    // buf pb: src=+pb*256, dst=+pb*256+128
    float* sBE1 = (float*)(smem + E_BE1);
    float* sBE2 = (float*)(smem + E_BE2);
    float* sStg = (float*)(smem + E_H);

    if (tid < D_HID) { sBE1[tid] = be1[tid]; sBE2[tid] = be2[tid]; }

    // resident weights
    {
        const uint4* s1 = (const uint4*)g_B1h; uint4* d1 = (uint4*)(smem + E_W1);
        #pragma unroll
        for (int i = 0; i < 9; i++) d1[tid + i * 512] = s1[tid + i * 512];
        const uint4* s2 = (const uint4*)g_B2h; uint4* d2 = (uint4*)(smem + E_W2);
        #pragma unroll
        for (int i = 0; i < 4; i++) d2[tid + i * 512] = s2[tid + i * 512];
    }

    const int lo15 = lane & 15;
    const int hi   = lane >> 4;
    const int lo7  = lane & 7;
    uint32_t bXor[2];
    #pragma unroll
    for (int p = 0; p < 2; p++) bXor[p] = (uint32_t)(((wn * 4 + 2 * p + hi) ^ lo7) * 16);

    const uint32_t aBase0 = sb + E_A + ((32 * wm + lo15) * A_STRIDE + hi * 8) * 2;
    const uint32_t aBase1 = aBase0 + 16 * A_STRIDE * 2;
    const uint32_t hBase0 = sb + E_H + ((32 * wm + lo15) * H_STRIDE + hi * 8) * 2;
    const uint32_t hBase1 = hBase0 + 16 * H_STRIDE * 2;
    const uint32_t w1Base = sb + E_W1 + lo15 * 256;
    const uint32_t w2Base = sb + E_W2 + lo15 * 256;

    const int rowLo = 32 * wm + (lane >> 2);
    const int colLo = wn * 32 + (lane & 3) * 2;

    int t = blockIdx.x;
    int pb = 0;
    // prologue: idx(t) into buf 0
    if (tid < TILE_E)            sIdx[tid] = eidx[t * TILE_E + tid];
    else if (tid < 2 * TILE_E)   sIdx[tid] = eidx[N_EDGES + t * TILE_E + (tid - TILE_E)];
    __syncthreads();
    // gather(t): 128 rows x 36 16B units = 4608 cp.async
    {
        const int* sS = sIdx, *sD = sIdx + TILE_E;
        #pragma unroll
        for (int it = 0; it < 9; it++) {
            int i = tid + it * ETHREADS;
            int row = i / 36, u = i - row * 36;
            const void* src;
            if (u < 16)      src = g_xh + (size_t)sS[row] * D_IN + u * 8;
            else if (u < 32) src = g_xh + (size_t)sD[row] * D_IN + (u - 16) * 8;
            else             src = g_eah + (size_t)(t * TILE_E + row) * D_EDGE + (u - 32) * 8;
            cpa16(sb + E_A + row * 592 + u * 16, src);
        }
        CPA_COMMIT();
    }

    for (; t < NT2; t += EDGE_GRID, pb ^= 1) {
        const int tn = t + EDGE_GRID;
        // load idx(tn) into buf pb^1
        if (tn < NT2) {
            if (tid < TILE_E)          sIdx[(pb ^ 1) * 256 + tid] = eidx[tn * TILE_E + tid];
            else if (tid < 2 * TILE_E) sIdx[(pb ^ 1) * 256 + tid] =
                                           eidx[N_EDGES + tn * TILE_E + (tid - TILE_E)];
        }
        CPA_WAIT0();
        __syncthreads();   // A(t) ready; idx(tn) visible

        float c[2][4][4];
        #pragma unroll
        for (int mi = 0; mi < 2; mi++)
            #pragma unroll
            for (int nt = 0; nt < 4; nt++)
                #pragma unroll
                for (int j = 0; j < 4; j++) c[mi][nt][j] = 0.0f;

        // ---- layer 1: K = 288 ----
        #pragma unroll
        for (int ks = 0; ks < 18; ks++) {
            uint32_t a0[4], a1[4];
            ldm_x4(a0, aBase0 + ks * 32);
            ldm_x4(a1, aBase1 + ks * 32);
            uint32_t bk = w1Base + ks * 4096;
            #pragma unroll
            for (int p = 0; p < 2; p++) {
                uint32_t b[4];
                ldm_x4_t(b, bk + bXor[p]);
                mma16816(c[0][2 * p + 0], a0, b[0], b[1]);
                mma16816(c[0][2 * p + 1], a0, b[2], b[3]);
                mma16816(c[1][2 * p + 0], a1, b[0], b[1]);
                mma16816(c[1][2 * p + 1], a1, b[2], b[3]);
            }
        }
        __syncthreads();   // all layer-1 A reads done -> A free

        // issue gather(tn) into A (overlaps epilogue1 + layer2 + scatter)
        if (tn < NT2) {
            const int* sS = sIdx + (pb ^ 1) * 256, *sD = sS + TILE_E;
            #pragma unroll
            for (int it = 0; it < 9; it++) {
                int i = tid + it * ETHREADS;
                int row = i / 36, u = i - row * 36;
                const void* src;
                if (u < 16)      src = g_xh + (size_t)sS[row] * D_IN + u * 8;
                else if (u < 32) src = g_xh + (size_t)sD[row] * D_IN + (u - 16) * 8;
                else             src = g_eah + (size_t)(tn * TILE_E + row) * D_EDGE + (u - 32) * 8;
                cpa16(sb + E_A + row * 592 + u * 16, src);
            }
            CPA_COMMIT();
        }

        // epilogue 1: bias+relu -> fp16 H
        #pragma unroll
        for (int mi = 0; mi < 2; mi++) {
            int r0 = rowLo + 16 * mi;
            #pragma unroll
            for (int nt = 0; nt < 4; nt++) {
                int col = nt * 8 + colLo;
                float2 bb = *(const float2*)(sBE1 + col);
                float v0 = fmaxf(c[mi][nt][0] + bb.x, 0.f);
                float v1 = fmaxf(c[mi][nt][1] + bb.y, 0.f);
                float v2 = fmaxf(c[mi][nt][2] + bb.x, 0.f);
                float v3 = fmaxf(c[mi][nt][3] + bb.y, 0.f);
                *(uint32_t*)(smem + E_H + (r0 * H_STRIDE + col) * 2) =
                    h2_bits(__floats2half2_rn(v0, v1));
                *(uint32_t*)(smem + E_H + ((r0 + 8) * H_STRIDE + col) * 2) =
                    h2_bits(__floats2half2_rn(v2, v3));
            }
        }
        __syncthreads();   // H visible

        #pragma unroll
        for (int mi = 0; mi < 2; mi++)
            #pragma unroll
            for (int nt = 0; nt < 4; nt++)
                #pragma unroll
                for (int j = 0; j < 4; j++) c[mi][nt][j] = 0.0f;

        // ---- layer 2: K = 128 ----
        #pragma unroll
        for (int ks = 0; ks < 8; ks++) {
            uint32_t a0[4], a1[4];
            ldm_x4(a0, hBase0 + ks * 32);
            ldm_x4(a1, hBase1 + ks * 32);
            uint32_t bk = w2Base + ks * 4096;
            #pragma unroll
            for (int p = 0; p < 2; p++) {
                uint32_t b[4];
                ldm_x4_t(b, bk + bXor[p]);
                mma16816(c[0][2 * p + 0], a0, b[0], b[1]);
                mma16816(c[0][2 * p + 1], a0, b[2], b[3]);
                mma16816(c[1][2 * p + 0], a1, b[0], b[1]);
                mma16816(c[1][2 * p + 1], a1, b[2], b[3]);
            }
        }
        __syncthreads();   // all H reads done before staging overwrites

        const int* sDstP = sIdx + pb * 256 + TILE_E;

        // epilogue 2: two 64-col passes through f32 staging -> v4 scatter
        #pragma unroll
        for (int p = 0; p < 2; p++) {
            if ((wn >> 1) == p) {
                #pragma unroll
                for (int mi = 0; mi < 2; mi++) {
                    int r0 = rowLo + 16 * mi;
                    #pragma unroll
                    for (int nt = 0; nt < 4; nt++) {
                        int col = nt * 8 + colLo;
                        int cl = col & 63;
                        float2 bb = *(const float2*)(sBE2 + col);
                        *(float2*)(sStg + r0 * STG_STRIDE + cl) =
                            make_float2(fmaxf(c[mi][nt][0] + bb.x, 0.f),
                                        fmaxf(c[mi][nt][1] + bb.y, 0.f));
                        *(float2*)(sStg + (r0 + 8) * STG_STRIDE + cl) =
                            make_float2(fmaxf(c[mi][nt][2] + bb.x, 0.f),
                                        fmaxf(c[mi][nt][3] + bb.y, 0.f));
                    }
                }
            }
            __syncthreads();
            #pragma unroll
            for (int i = 0; i < 4; i++) {
                int v = tid + i * ETHREADS;      // 2048 v4 slots
                int row = v >> 4, c4 = v & 15;
                float4 val = *(const float4*)(sStg + row * STG_STRIDE + c4 * 4);
                red_add_v4(g_agg + (size_t)sDstP[row] * D_HID + p * 64 + c4 * 4,
                           val.x, val.y, val.z, val.w);
            }
            __syncthreads();
        }
    }
}

// ============================================================================
// Node block: HMMA fp16 (unchanged, passing).
// ============================================================================
__global__ __launch_bounds__(256, 2) void node_kernel(
    const float* __restrict__ x,
    const float* __restrict__ bg, const float* __restrict__ bn,
    const int* __restrict__ batch, float* __restrict__ xw_out)
{
    extern __shared__ char smem[];
    const uint32_t sb = smem_u32(smem);
    const int tid = threadIdx.x, wid = tid >> 5, lane = tid & 31;
    const int wm = wid & 3, wn = wid >> 2;
    const int nBase = blockIdx.x * TILE_M;

    float* sBG = (float*)(smem + N_BG);
    float* sBN = (float*)(smem + N_BN);
    if (tid < D_HID) { sBG[tid] = bg[tid]; sBN[tid] = bn[tid]; }

    const int lo15 = lane & 15;
    const int hi   = lane >> 4;
    const int lo7  = lane & 7;
    uint32_t bXor[4];
    #pragma unroll
    for (int p = 0; p < 4; p++) bXor[p] = (uint32_t)(((wn * 8 + 2 * p + hi) ^ lo7) * 16);

    const uint32_t aBase = sb + N_A + ((16 * wm + lo15) * A_STRIDE + hi * 8) * 2;
    const uint32_t wBase = sb + N_W + lo15 * 256;

    const int rowLo = 16 * wm + (lane >> 2);
    const int rowHi = rowLo + 8;
    const int colLo = wn * 64 + (lane & 3) * 2;
    const int nLo = nBase + rowLo, nHi = nBase + rowHi;
    const int bLo = batch[min(nLo, N_NODES - 1)];
    const int bHi = batch[min(nHi, N_NODES - 1)];

    #pragma unroll
    for (int it = 0; it < 16; it++) {
        int i = tid + it * 256;
        int row = i >> 6, u = i & 63;
        int k0 = u * 4;
        int n = min(nBase + row, N_NODES - 1);
        float4 v = (k0 < D_IN)
            ? __ldg((const float4*)(x + (size_t)n * D_IN + k0))
            : *(const float4*)(g_agg + (size_t)n * D_HID + (k0 - D_IN));
        __half2 h0 = __floats2half2_rn(v.x, v.y);
        __half2 h1 = __floats2half2_rn(v.z, v.w);
        *reinterpret_cast<uint2*>(smem + N_A + (row * A_STRIDE + k0) * 2) =
            make_uint2(h2_bits(h0), h2_bits(h1));
    }
    {
        const uint4* s = (const uint4*)g_Bgh; uint4* d = (uint4*)(smem + N_W);
        #pragma unroll
        for (int i = 0; i < 16; i++) d[tid + i * 256] = s[tid + i * 256];
    }
    __syncthreads();

    float c[8][4];
    #pragma unroll
    for (int nt = 0; nt < 8; nt++)
        #pragma unroll
        for (int j = 0; j < 4; j++) c[nt][j] = 0.0f;

    #pragma unroll
    for (int ks = 0; ks < 16; ks++) {
        uint32_t a[4];
        ldm_x4(a, aBase + ks * 32);
        uint32_t bk = wBase + ks * 4096;
        #pragma unroll
        for (int p = 0; p < 4; p++) {
            uint32_t b[4];
            ldm_x4_t(b, bk + bXor[p]);
            mma16816(c[2 * p + 0], a, b[0], b[1]);
            mma16816(c[2 * p + 1], a, b[2], b[3]);
        }
    }

    float gate[8][4];
    #pragma unroll
    for (int nt = 0; nt < 8; nt++) {
        int col = nt * 8 + colLo;
        float2 bb = *(const float2*)(sBG + col);
        gate[nt][0] = 1.0f / (1.0f + __expf(-(c[nt][0] + bb.x)));
        gate[nt][1] = 1.0f / (1.0f + __expf(-(c[nt][1] + bb.y)));
        gate[nt][2] = 1.0f / (1.0f + __expf(-(c[nt][2] + bb.x)));
        gate[nt][3] = 1.0f / (1.0f + __expf(-(c[nt][3] + bb.y)));
        if (nLo < N_NODES)
            *(float2*)(xw_out + (size_t)nLo * D_HID + col) = make_float2(gate[nt][0], gate[nt][1]);
        if (nHi < N_NODES)
            *(float2*)(xw_out + (size_t)nHi * D_HID + col) = make_float2(gate[nt][2], gate[nt][3]);
    }
    if (wn == 0 && (lane & 3) == 0) {
        if (nLo < N_NODES) atomicAdd(&g_counts[bLo], 1.0f);
        if (nHi < N_NODES) atomicAdd(&g_counts[bHi], 1.0f);
    }

    __syncthreads();
    {
        const uint4* s = (const uint4*)g_Bnh; uint4* d = (uint4*)(smem + N_W);
        #pragma unroll
        for (int i = 0; i < 16; i++) d[tid + i * 256] = s[tid + i * 256];
    }
    __syncthreads();

    #pragma unroll
    for (int nt = 0; nt < 8; nt++)
        #pragma unroll
        for (int j = 0; j < 4; j++) c[nt][j] = 0.0f;

    #pragma unroll
    for (int ks = 0; ks < 16; ks++) {
        uint32_t a[4];
        ldm_x4(a, aBase + ks * 32);
        uint32_t bk = wBase + ks * 4096;
        #pragma unroll
        for (int p = 0; p < 4; p++) {
            uint32_t b[4];
            ldm_x4_t(b, bk + bXor[p]);
            mma16816(c[2 * p + 0], a, b[0], b[1]);
            mma16816(c[2 * p + 1], a, b[2], b[3]);
        }
    }

    #pragma unroll
    for (int nt = 0; nt < 8; nt++) {
        int col = nt * 8 + colLo;
        float2 bb = *(const float2*)(sBN + col);
        float x0 = gate[nt][0] * fmaxf(c[nt][0] + bb.x, 0.f);
        float x1 = gate[nt][1] * fmaxf(c[nt][1] + bb.y, 0.f);
        float x2 = gate[nt][2] * fmaxf(c[nt][2] + bb.x, 0.f);
        float x3 = gate[nt][3] * fmaxf(c[nt][3] + bb.y, 0.f);
        if (nLo < N_NODES) red_add_v2(g_pooled + (size_t)bLo * D_HID + col, x0, x1);
        if (nHi < N_NODES) red_add_v2(g_pooled + (size_t)bHi * D_HID + col, x2, x3);
    }
}

// ---------------------------------------------------------------------------
__global__ __launch_bounds__(64) void global_kernel(
    const float* __restrict__ u, const float* __restrict__ Wu,
    const float* __restrict__ bu, float* __restrict__ out)
{
    __shared__ float sin_[D_GLOB + D_HID];
    int g = blockIdx.x;
    int j = threadIdx.x;
    float cnt = fmaxf(g_counts[g], 1.0f);
    sin_[j] = u[g * D_GLOB + j];
    sin_[D_GLOB + j]      = g_pooled[g * D_HID + j] / cnt;
    sin_[D_GLOB + 64 + j] = g_pooled[g * D_HID + 64 + j] / cnt;
    __syncthreads();
    float acc = bu[j];
    #pragma unroll 8
    for (int k = 0; k < D_GLOB + D_HID; k++)
        acc = fmaf(sin_[k], Wu[k * D_GLOB + j], acc);
    out[g * D_GLOB + j] = fmaxf(acc, 0.0f);
}

// ---------------------------------------------------------------------------
extern "C" void kernel_launch(void* const* d_in, const int* in_sizes, int n_in,
                              void* d_out, int out_size)
{
    const float* x    = (const float*)d_in[0];
    const int*   eidx = (const int*)  d_in[1];
    const float* ea   = (const float*)d_in[2];
    const float* u    = (const float*)d_in[3];
    const int*   batch= (const int*)  d_in[4];
    const float* We1  = (const float*)d_in[5];
    const float* be1  = (const float*)d_in[6];
    const float* We2  = (const float*)d_in[7];
    const float* be2  = (const float*)d_in[8];
    const float* Wg   = (const float*)d_in[9];
    const float* bg   = (const float*)d_in[10];
    const float* Wn   = (const float*)d_in[11];
    const float* bn   = (const float*)d_in[12];
    const float* Wu   = (const float*)d_in[13];
    const float* bu   = (const float*)d_in[14];

    float* out   = (float*)d_out;
    float* u_new = out;
    float* xw    = out + N_GRAPHS * D_GLOB;

    cudaFuncSetAttribute(edge_kernel, cudaFuncAttributeMaxDynamicSharedMemorySize, E_TOTAL);
    cudaFuncSetAttribute(node_kernel, cudaFuncAttributeMaxDynamicSharedMemorySize, N_TOTAL);

    zero_kernel<<<2048, 256>>>();
    prep_xe<<<2048, 256>>>(x, ea);
    int prep_elems = K1 * D_HID + D_HID * D_HID + 4 * D_HID * D_HID;
    prep_w<<<(prep_elems + 255) / 256, 256>>>(We1, We2, Wg, Wn);
    edge_kernel<<<EDGE_GRID, ETHREADS, E_TOTAL>>>(eidx, be1, be2);
    node_kernel<<<(N_NODES + TILE_M - 1) / TILE_M, 256, N_TOTAL>>>(x, bg, bn, batch, xw);
    global_kernel<<<N_GRAPHS, 64>>>(u, Wu, bu, u_new);
}